// round 9
// baseline (speedup 1.0000x reference)
#include <cuda_runtime.h>
#include <cuda_bf16.h>
#include <math.h>
#include <stdint.h>

#define S_LEN 4096
#define DMODEL 768
#define NH 12
#define DK 64
#define XN (S_LEN * DMODEL)
#define WN (DMODEL * DMODEL)

__device__ __nv_bfloat16 g_xh[3 * XN], g_xl[3 * XN];
__device__ __nv_bfloat16 g_wh[2 * WN], g_wl[2 * WN];
__device__ __nv_bfloat16 g_qh[XN], g_ql[XN], g_kh[XN], g_kl[XN], g_vh[XN], g_vl[XN];
__device__ __nv_bfloat16 g_ah[XN], g_al[XN];

__device__ __forceinline__ uint32_t smem_u32(const void* p) {
    uint32_t a;
    asm("{ .reg .u64 t; cvta.to.shared.u64 t, %1; cvt.u32.u64 %0, t; }" : "=r"(a) : "l"(p));
    return a;
}
__device__ __forceinline__ float ex2f(float x) {
    float r; asm("ex2.approx.ftz.f32 %0, %1;" : "=f"(r) : "f"(x)); return r;
}
__device__ __forceinline__ uint32_t pack_bf16(float a, float b) {  // low=a, high=b
    uint32_t r; asm("cvt.rn.satfinite.bf16x2.f32 %0, %1, %2;" : "=r"(r) : "f"(b), "f"(a)); return r;
}
__device__ __forceinline__ void ldsm4(uint32_t* r, uint32_t a) {
    asm volatile("ldmatrix.sync.aligned.m8n8.x4.shared.b16 {%0,%1,%2,%3}, [%4];"
                 : "=r"(r[0]), "=r"(r[1]), "=r"(r[2]), "=r"(r[3]) : "r"(a));
}
__device__ __forceinline__ void ldsm4t(uint32_t* r, uint32_t a) {
    asm volatile("ldmatrix.sync.aligned.m8n8.x4.trans.shared.b16 {%0,%1,%2,%3}, [%4];"
                 : "=r"(r[0]), "=r"(r[1]), "=r"(r[2]), "=r"(r[3]) : "r"(a));
}
__device__ __forceinline__ void mma16816(float* d, const uint32_t* a, const uint32_t* b) {
    asm volatile("mma.sync.aligned.m16n8k16.row.col.f32.bf16.bf16.f32 "
                 "{%0,%1,%2,%3}, {%4,%5,%6,%7}, {%8,%9}, {%0,%1,%2,%3};"
                 : "+f"(d[0]), "+f"(d[1]), "+f"(d[2]), "+f"(d[3])
                 : "r"(a[0]), "r"(a[1]), "r"(a[2]), "r"(a[3]), "r"(b[0]), "r"(b[1]));
}
__device__ __forceinline__ void cp16(uint32_t d, const void* s) {
    asm volatile("cp.async.cg.shared.global [%0], [%1], 16;" :: "r"(d), "l"(s));
}
#define CP_COMMIT() asm volatile("cp.async.commit_group;" ::: "memory")
#define CP_WAIT0()  asm volatile("cp.async.wait_group 0;" ::: "memory")

__global__ void conv_hilo(const float* __restrict__ in, __nv_bfloat16* __restrict__ hi,
                          __nv_bfloat16* __restrict__ lo, int n4)
{
    int i = blockIdx.x * blockDim.x + threadIdx.x;
    if (i >= n4) return;
    float4 v = ((const float4*)in)[i];
    uint32_t h01 = pack_bf16(v.x, v.y), h23 = pack_bf16(v.z, v.w);
    __nv_bfloat162 a = *(__nv_bfloat162*)&h01, b = *(__nv_bfloat162*)&h23;
    ((uint32_t*)hi)[2 * i] = h01; ((uint32_t*)hi)[2 * i + 1] = h23;
    ((uint32_t*)lo)[2 * i]     = pack_bf16(v.x - __bfloat162float(a.x), v.y - __bfloat162float(a.y));
    ((uint32_t*)lo)[2 * i + 1] = pack_bf16(v.z - __bfloat162float(b.x), v.w - __bfloat162float(b.y));
}

// ---------------------------------------------------------------------------
// Projection GEMM core: cp.async 2-stage pipeline, 128x128 tile, 8 warps.
// ---------------------------------------------------------------------------
#define PM 5120
#define PSTG (4 * PM)
#define PROJ_SMEM (2 * PSTG * 2)

__device__ __forceinline__ void proj_stage_load(
    __nv_bfloat16* st, const __nv_bfloat16* Xh, const __nv_bfloat16* Xl,
    const __nv_bfloat16* Wh, const __nv_bfloat16* Wl,
    int m0, int n0, int k0, int tid)
{
    #pragma unroll
    for (int i = 0; i < 2; i++) {
        int idx = tid + i * 256;
        int r = idx >> 2, c8 = (idx & 3) * 8;
        size_t xs = (size_t)(m0 + r) * DMODEL + k0 + c8;
        size_t ws = (size_t)(n0 + r) * DMODEL + k0 + c8;
        uint32_t base = smem_u32(st + r * 40 + c8);
        cp16(base,               Xh + xs);
        cp16(base + PM * 2,      Xl + xs);
        cp16(base + 2 * PM * 2,  Wh + ws);
        cp16(base + 3 * PM * 2,  Wl + ws);
    }
    CP_COMMIT();
}

__device__ __forceinline__ void proj_gemm(
    float acc[2][8][4], __nv_bfloat16* sm,
    const __nv_bfloat16* Xh, const __nv_bfloat16* Xl,
    const __nv_bfloat16* Wh, const __nv_bfloat16* Wl,
    int m0, int n0, int tid, int wm, int wn, int lid)
{
    proj_stage_load(sm, Xh, Xl, Wh, Wl, m0, n0, 0, tid);
    for (int t = 0; t < DMODEL / 32; t++) {
        CP_WAIT0();
        __syncthreads();
        if (t + 1 < DMODEL / 32)
            proj_stage_load(sm + ((t + 1) & 1) * PSTG, Xh, Xl, Wh, Wl, m0, n0, (t + 1) * 32, tid);
        __nv_bfloat16* Ahs = sm + (t & 1) * PSTG;
        __nv_bfloat16* Als = Ahs + PM;
        __nv_bfloat16* Bhs = Ahs + 2 * PM;
        __nv_bfloat16* Bls = Ahs + 3 * PM;
        #pragma unroll
        for (int ks = 0; ks < 32; ks += 16) {
            const int ac = ks + ((lid >> 4) << 3);
            uint32_t ah[2][4], al[2][4], bh[8][2], bl[8][2], r4[4];
            #pragma unroll
            for (int jp = 0; jp < 4; jp++) {
                int rB = 64 * wn + 16 * jp + (lid & 15);
                ldsm4(r4, smem_u32(Bhs + rB * 40 + ac));
                bh[2*jp][0]=r4[0]; bh[2*jp][1]=r4[2]; bh[2*jp+1][0]=r4[1]; bh[2*jp+1][1]=r4[3];
                ldsm4(r4, smem_u32(Bls + rB * 40 + ac));
                bl[2*jp][0]=r4[0]; bl[2*jp][1]=r4[2]; bl[2*jp+1][0]=r4[1]; bl[2*jp+1][1]=r4[3];
            }
            #pragma unroll
            for (int i = 0; i < 2; i++) {
                int rA = 32 * wm + 16 * i + (lid & 15);
                ldsm4(ah[i], smem_u32(Ahs + rA * 40 + ac));
                ldsm4(al[i], smem_u32(Als + rA * 40 + ac));
            }
            #pragma unroll
            for (int i = 0; i < 2; i++)
                #pragma unroll
                for (int j = 0; j < 8; j++) {
                    mma16816(acc[i][j], ah[i], bh[j]);
                    mma16816(acc[i][j], ah[i], bl[j]);
                    mma16816(acc[i][j], al[i], bh[j]);
                }
        }
        __syncthreads();
    }
}

__global__ void __launch_bounds__(256, 2) qkv_proj(
    const __nv_bfloat16* __restrict__ xh, const __nv_bfloat16* __restrict__ xl,
    const __nv_bfloat16* __restrict__ Wh, const __nv_bfloat16* __restrict__ Wl,
    const float* __restrict__ bias,
    __nv_bfloat16* __restrict__ Qh, __nv_bfloat16* __restrict__ Ql,
    __nv_bfloat16* __restrict__ Kh, __nv_bfloat16* __restrict__ Kl,
    __nv_bfloat16* __restrict__ Vh, __nv_bfloat16* __restrict__ Vl)
{
    extern __shared__ __nv_bfloat16 sm[];
    const int tid = threadIdx.x, w = tid >> 5, lid = tid & 31;
    const int wm = w >> 1, wn = w & 1;
    const int m0 = blockIdx.y * 128, n0 = blockIdx.x * 128, z = blockIdx.z;
    const __nv_bfloat16* Xh = xh + (size_t)z * XN;
    const __nv_bfloat16* Xl = xl + (size_t)z * XN;
    __nv_bfloat16* Yh = (z == 0) ? Qh : (z == 1) ? Kh : Vh;
    __nv_bfloat16* Yl = (z == 0) ? Ql : (z == 1) ? Kl : Vl;
    const float sc = (z == 0) ? 0.18033688011112042f : 1.0f;  // 0.125*log2(e)

    float acc[2][8][4] = {};
    proj_gemm(acc, sm, Xh, Xl, Wh, Wl, m0, n0, tid, wm, wn, lid);

    #pragma unroll
    for (int i = 0; i < 2; i++) {
        int r = m0 + 32 * wm + 16 * i + (lid >> 2);
        #pragma unroll
        for (int j = 0; j < 8; j++) {
            int ng = n0 + 64 * wn + 8 * j + (lid & 3) * 2;
            float b0 = bias[ng], b1 = bias[ng + 1];
            int head = ng >> 6;
            #pragma unroll
            for (int hrow = 0; hrow < 2; hrow++) {
                int rr = r + hrow * 8;
                float f0 = (acc[i][j][2*hrow]   + b0) * sc;
                float f1 = (acc[i][j][2*hrow+1] + b1) * sc;
                uint32_t hp = pack_bf16(f0, f1);
                __nv_bfloat162 u = *(__nv_bfloat162*)&hp;
                size_t dst = ((size_t)head * S_LEN + rr) * DK + (ng & 63);
                *(uint32_t*)(Yh + dst) = hp;
                *(uint32_t*)(Yl + dst) = pack_bf16(f0 - __bfloat162float(u.x),
                                                   f1 - __bfloat162float(u.y));
            }
        }
    }
}

__global__ void __launch_bounds__(256, 2) out_proj(
    const __nv_bfloat16* __restrict__ Xh, const __nv_bfloat16* __restrict__ Xl,
    const __nv_bfloat16* __restrict__ Wh, const __nv_bfloat16* __restrict__ Wl,
    const float* __restrict__ bias, float* __restrict__ Yf)
{
    extern __shared__ __nv_bfloat16 sm[];
    const int tid = threadIdx.x, w = tid >> 5, lid = tid & 31;
    const int wm = w >> 1, wn = w & 1;
    const int m0 = blockIdx.y * 128, n0 = blockIdx.x * 128;

    float acc[2][8][4] = {};
    proj_gemm(acc, sm, Xh, Xl, Wh, Wl, m0, n0, tid, wm, wn, lid);

    #pragma unroll
    for (int i = 0; i < 2; i++) {
        int r = m0 + 32 * wm + 16 * i + (lid >> 2);
        #pragma unroll
        for (int j = 0; j < 8; j++) {
            int ng = n0 + 64 * wn + 8 * j + (lid & 3) * 2;
            float b0 = bias[ng], b1 = bias[ng + 1];
            #pragma unroll
            for (int hrow = 0; hrow < 2; hrow++) {
                int rr = r + hrow * 8;
                Yf[(size_t)rr * DMODEL + ng]     = acc[i][j][2*hrow]   + b0;
                Yf[(size_t)rr * DMODEL + ng + 1] = acc[i][j][2*hrow+1] + b1;
            }
        }
    }
}

// ---------------------------------------------------------------------------
// Flash attention: CTA = (head, 64 q rows), 4 warps x 16 rows, Bc=64.
// smem 90KB -> 2 CTAs/SM; independent CTAs interleave softmax and MMA phases.
// ---------------------------------------------------------------------------
#define QS 72
#define AT_SMEM ((128 + 512) * QS * 2)   // Q hi/lo (128 rows) + 2 KV stages (512 rows)
__global__ void __launch_bounds__(128, 2) attn_tc(
    const __nv_bfloat16* __restrict__ Qh, const __nv_bfloat16* __restrict__ Ql,
    const __nv_bfloat16* __restrict__ Kh, const __nv_bfloat16* __restrict__ Kl,
    const __nv_bfloat16* __restrict__ Vh, const __nv_bfloat16* __restrict__ Vl,
    __nv_bfloat16* __restrict__ Ah, __nv_bfloat16* __restrict__ Al)
{
    extern __shared__ __nv_bfloat16 sm[];
    __nv_bfloat16 (*Qhs)[QS] = (__nv_bfloat16(*)[QS])sm;   // 64 rows
    __nv_bfloat16 (*Qls)[QS] = Qhs + 64;
    __nv_bfloat16 (*KV0)[QS] = Qls + 64;                    // stage: K,Kl,V,Vl 64 rows each

    const int tid = threadIdx.x, w = tid >> 5, lid = tid & 31;
    const int h = blockIdx.y, q0 = blockIdx.x * 64;

    #pragma unroll
    for (int i = 0; i < 4; i++) {              // Q: 512 uint4 over 128 threads
        int idx = tid + i * 128;
        int r = idx >> 3, c8 = (idx & 7) * 8;
        size_t src = ((size_t)h * S_LEN + q0 + r) * DK + c8;
        *(uint4*)&Qhs[r][c8] = *(const uint4*)(Qh + src);
        *(uint4*)&Qls[r][c8] = *(const uint4*)(Ql + src);
    }
    {
        __nv_bfloat16 (*S0)[QS] = KV0;
        #pragma unroll
        for (int i = 0; i < 4; i++) {
            int idx = tid + i * 128;
            int r = idx >> 3, c8 = (idx & 7) * 8;
            size_t src = ((size_t)h * S_LEN + r) * DK + c8;
            cp16(smem_u32(&S0[r][c8]),       Kh + src);
            cp16(smem_u32(&S0[64 + r][c8]),  Kl + src);
            cp16(smem_u32(&S0[128 + r][c8]), Vh + src);
            cp16(smem_u32(&S0[192 + r][c8]), Vl + src);
        }
        CP_COMMIT();
    }

    float O[8][4] = {};
    float m0r = -INFINITY, m1r = -INFINITY, l0r = 0.f, l1r = 0.f;

    for (int t = 0; t < S_LEN / 64; t++) {
        CP_WAIT0();
        __syncthreads();
        if (t + 1 < S_LEN / 64) {
            __nv_bfloat16 (*SN)[QS] = KV0 + ((t + 1) & 1) * 256;
            int kvn = (t + 1) * 64;
            #pragma unroll
            for (int i = 0; i < 4; i++) {
                int idx = tid + i * 128;
                int r = idx >> 3, c8 = (idx & 7) * 8;
                size_t src = ((size_t)h * S_LEN + kvn + r) * DK + c8;
                cp16(smem_u32(&SN[r][c8]),       Kh + src);
                cp16(smem_u32(&SN[64 + r][c8]),  Kl + src);
                cp16(smem_u32(&SN[128 + r][c8]), Vh + src);
                cp16(smem_u32(&SN[192 + r][c8]), Vl + src);
            }
            CP_COMMIT();
        }
        __nv_bfloat16 (*Khs)[QS] = KV0 + (t & 1) * 256;
        __nv_bfloat16 (*Kls)[QS] = Khs + 64;
        __nv_bfloat16 (*Vhs)[QS] = Khs + 128;
        __nv_bfloat16 (*Vls)[QS] = Khs + 192;

        float s[8][4] = {};
        #pragma unroll
        for (int ks = 0; ks < 4; ks++) {
            const int ac = 16 * ks + ((lid >> 4) << 3);
            uint32_t ahf[4], alf[4], bh[8][2], bl[8][2], r4[4];
            ldsm4(ahf, smem_u32(&Qhs[16 * w + (lid & 15)][ac]));
            ldsm4(alf, smem_u32(&Qls[16 * w + (lid & 15)][ac]));
            #pragma unroll
            for (int jp = 0; jp < 4; jp++) {
                int rB = 16 * jp + (lid & 15);
                ldsm4(r4, smem_u32(&Khs[rB][ac]));
                bh[2*jp][0]=r4[0]; bh[2*jp][1]=r4[2]; bh[2*jp+1][0]=r4[1]; bh[2*jp+1][1]=r4[3];
                ldsm4(r4, smem_u32(&Kls[rB][ac]));
                bl[2*jp][0]=r4[0]; bl[2*jp][1]=r4[2]; bl[2*jp+1][0]=r4[1]; bl[2*jp+1][1]=r4[3];
            }
            #pragma unroll
            for (int j = 0; j < 8; j++) {
                mma16816(s[j], ahf, bh[j]);
                mma16816(s[j], ahf, bl[j]);
                mma16816(s[j], alf, bh[j]);
            }
        }

        float rm0 = -INFINITY, rm1 = -INFINITY;
        #pragma unroll
        for (int j = 0; j < 8; j++) {
            rm0 = fmaxf(rm0, fmaxf(s[j][0], s[j][1]));
            rm1 = fmaxf(rm1, fmaxf(s[j][2], s[j][3]));
        }
        rm0 = fmaxf(rm0, __shfl_xor_sync(~0u, rm0, 1)); rm0 = fmaxf(rm0, __shfl_xor_sync(~0u, rm0, 2));
        rm1 = fmaxf(rm1, __shfl_xor_sync(~0u, rm1, 1)); rm1 = fmaxf(rm1, __shfl_xor_sync(~0u, rm1, 2));
        float mn0 = fmaxf(m0r, rm0), mn1 = fmaxf(m1r, rm1);
        float c0 = ex2f(m0r - mn0), c1 = ex2f(m1r - mn1);
        m0r = mn0; m1r = mn1;
        float s0 = 0.f, s1 = 0.f;
        #pragma unroll
        for (int j = 0; j < 8; j++) {
            s[j][0] = ex2f(s[j][0] - mn0); s[j][1] = ex2f(s[j][1] - mn0);
            s[j][2] = ex2f(s[j][2] - mn1); s[j][3] = ex2f(s[j][3] - mn1);
            s0 += s[j][0] + s[j][1]; s1 += s[j][2] + s[j][3];
        }
        s0 += __shfl_xor_sync(~0u, s0, 1); s0 += __shfl_xor_sync(~0u, s0, 2);
        s1 += __shfl_xor_sync(~0u, s1, 1); s1 += __shfl_xor_sync(~0u, s1, 2);
        l0r = l0r * c0 + s0; l1r = l1r * c1 + s1;
        #pragma unroll
        for (int j = 0; j < 8; j++) { O[j][0] *= c0; O[j][1] *= c0; O[j][2] *= c1; O[j][3] *= c1; }

        uint32_t ph[4][4], pl[4][4];
        #pragma unroll
        for (int j2 = 0; j2 < 4; j2++) {
            int t0 = 2 * j2, t1 = t0 + 1;
            ph[j2][0] = pack_bf16(s[t0][0], s[t0][1]); ph[j2][1] = pack_bf16(s[t0][2], s[t0][3]);
            ph[j2][2] = pack_bf16(s[t1][0], s[t1][1]); ph[j2][3] = pack_bf16(s[t1][2], s[t1][3]);
            #pragma unroll
            for (int q = 0; q < 4; q++) {
                __nv_bfloat162 u = *(__nv_bfloat162*)&ph[j2][q];
                const float* sv = (q < 2) ? s[t0] : s[t1];
                int b = (q & 1) * 2;
                pl[j2][q] = pack_bf16(sv[b] - __bfloat162float(u.x),
                                      sv[b + 1] - __bfloat162float(u.y));
            }
        }

        #pragma unroll
        for (int j2 = 0; j2 < 4; j2++) {
            uint32_t vh[8][2], vl[8][2], r4[4];
            #pragma unroll
            for (int np = 0; np < 4; np++) {
                int rV = 16 * j2 + (lid & 15), cV = 16 * np + ((lid >> 4) << 3);
                ldsm4t(r4, smem_u32(&Vhs[rV][cV]));
                vh[2*np][0]=r4[0]; vh[2*np][1]=r4[1]; vh[2*np+1][0]=r4[2]; vh[2*np+1][1]=r4[3];
                ldsm4t(r4, smem_u32(&Vls[rV][cV]));
                vl[2*np][0]=r4[0]; vl[2*np][1]=r4[1]; vl[2*np+1][0]=r4[2]; vl[2*np+1][1]=r4[3];
            }
            #pragma unroll
            for (int tt = 0; tt < 8; tt++) {
                mma16816(O[tt], ph[j2], vh[tt]);
                mma16816(O[tt], ph[j2], vl[tt]);
                mma16816(O[tt], pl[j2], vh[tt]);
            }
        }
    }

    float i0 = 1.f / l0r, i1 = 1.f / l1r;
    #pragma unroll
    for (int t = 0; t < 8; t++) {
        int c = h * DK + 8 * t + (lid & 3) * 2;
        int r0 = q0 + 16 * w + (lid >> 2);
        #pragma unroll
        for (int hrow = 0; hrow < 2; hrow++) {
            float f0 = O[t][2*hrow]   * (hrow ? i1 : i0);
            float f1 = O[t][2*hrow+1] * (hrow ? i1 : i0);
            uint32_t hp = pack_bf16(f0, f1);
            __nv_bfloat162 u = *(__nv_bfloat162*)&hp;
            size_t dst = (size_t)(r0 + hrow * 8) * DMODEL + c;
            *(uint32_t*)(Ah + dst) = hp;
            *(uint32_t*)(Al + dst) = pack_bf16(f0 - __bfloat162float(u.x),
                                               f1 - __bfloat162float(u.y));
        }
    }
}

extern "C" void kernel_launch(void* const* d_in, const int* in_sizes, int n_in,
                              void* d_out, int out_size)
{
    const float* q  = (const float*)d_in[0];
    const float* k  = (const float*)d_in[1];
    const float* v  = (const float*)d_in[2];
    const float* Wq = (const float*)d_in[3];
    const float* bq = (const float*)d_in[4];
    const float* Wo = (const float*)d_in[5];
    const float* bo = (const float*)d_in[6];
    float* out = (float*)d_out;

    __nv_bfloat16 *xh, *xl, *wh, *wl, *qh, *ql, *kh, *kl, *vh, *vl, *ah, *al;
    cudaGetSymbolAddress((void**)&xh, g_xh); cudaGetSymbolAddress((void**)&xl, g_xl);
    cudaGetSymbolAddress((void**)&wh, g_wh); cudaGetSymbolAddress((void**)&wl, g_wl);
    cudaGetSymbolAddress((void**)&qh, g_qh); cudaGetSymbolAddress((void**)&ql, g_ql);
    cudaGetSymbolAddress((void**)&kh, g_kh); cudaGetSymbolAddress((void**)&kl, g_kl);
    cudaGetSymbolAddress((void**)&vh, g_vh); cudaGetSymbolAddress((void**)&vl, g_vl);
    cudaGetSymbolAddress((void**)&ah, g_ah); cudaGetSymbolAddress((void**)&al, g_al);

    cudaFuncSetAttribute(attn_tc,  cudaFuncAttributeMaxDynamicSharedMemorySize, AT_SMEM);
    cudaFuncSetAttribute(qkv_proj, cudaFuncAttributeMaxDynamicSharedMemorySize, PROJ_SMEM);
    cudaFuncSetAttribute(out_proj, cudaFuncAttributeMaxDynamicSharedMemorySize, PROJ_SMEM);

    conv_hilo<<<XN / 4 / 256, 256>>>(q, xh,          xl,          XN / 4);
    conv_hilo<<<XN / 4 / 256, 256>>>(k, xh + XN,     xl + XN,     XN / 4);
    conv_hilo<<<XN / 4 / 256, 256>>>(v, xh + 2 * XN, xl + 2 * XN, XN / 4);
    conv_hilo<<<WN / 4 / 256, 256>>>(Wq, wh,      wl,      WN / 4);
    conv_hilo<<<WN / 4 / 256, 256>>>(Wo, wh + WN, wl + WN, WN / 4);

    dim3 gqkv(DMODEL / 128, S_LEN / 128, 3);   // 6 x 32 x 3
    qkv_proj<<<gqkv, 256, PROJ_SMEM>>>(xh, xl, wh, wl, bq, qh, ql, kh, kl, vh, vl);

    dim3 gattn(S_LEN / 64, NH);                // 64 x 12
    attn_tc<<<gattn, 128, AT_SMEM>>>(qh, ql, kh, kl, vh, vl, ah, al);

    dim3 gout(DMODEL / 128, S_LEN / 128);      // 6 x 32
    out_proj<<<gout, 256, PROJ_SMEM>>>(ah, al, wh + WN, wl + WN, bo, out);
}

// round 10
// speedup vs baseline: 1.0440x; 1.0440x over previous
#include <cuda_runtime.h>
#include <cuda_bf16.h>
#include <math.h>
#include <stdint.h>

#define S_LEN 4096
#define DMODEL 768
#define NH 12
#define DK 64
#define XN (S_LEN * DMODEL)
#define WN (DMODEL * DMODEL)

__device__ __nv_bfloat16 g_xh[3 * XN], g_xl[3 * XN];
__device__ __nv_bfloat16 g_wh[2 * WN], g_wl[2 * WN];
__device__ __nv_bfloat16 g_qh[XN], g_ql[XN], g_kh[XN], g_kl[XN], g_vh[XN], g_vl[XN];
__device__ __nv_bfloat16 g_ah[XN], g_al[XN];

__device__ __forceinline__ uint32_t smem_u32(const void* p) {
    uint32_t a;
    asm("{ .reg .u64 t; cvta.to.shared.u64 t, %1; cvt.u32.u64 %0, t; }" : "=r"(a) : "l"(p));
    return a;
}
__device__ __forceinline__ float ex2f(float x) {
    float r; asm("ex2.approx.ftz.f32 %0, %1;" : "=f"(r) : "f"(x)); return r;
}
__device__ __forceinline__ uint32_t pack_bf16(float a, float b) {  // low=a, high=b
    uint32_t r; asm("cvt.rn.satfinite.bf16x2.f32 %0, %1, %2;" : "=r"(r) : "f"(b), "f"(a)); return r;
}
__device__ __forceinline__ void ldsm4(uint32_t* r, uint32_t a) {
    asm volatile("ldmatrix.sync.aligned.m8n8.x4.shared.b16 {%0,%1,%2,%3}, [%4];"
                 : "=r"(r[0]), "=r"(r[1]), "=r"(r[2]), "=r"(r[3]) : "r"(a));
}
__device__ __forceinline__ void ldsm4t(uint32_t* r, uint32_t a) {
    asm volatile("ldmatrix.sync.aligned.m8n8.x4.trans.shared.b16 {%0,%1,%2,%3}, [%4];"
                 : "=r"(r[0]), "=r"(r[1]), "=r"(r[2]), "=r"(r[3]) : "r"(a));
}
__device__ __forceinline__ void mma16816(float* d, const uint32_t* a, const uint32_t* b) {
    asm volatile("mma.sync.aligned.m16n8k16.row.col.f32.bf16.bf16.f32 "
                 "{%0,%1,%2,%3}, {%4,%5,%6,%7}, {%8,%9}, {%0,%1,%2,%3};"
                 : "+f"(d[0]), "+f"(d[1]), "+f"(d[2]), "+f"(d[3])
                 : "r"(a[0]), "r"(a[1]), "r"(a[2]), "r"(a[3]), "r"(b[0]), "r"(b[1]));
}
__device__ __forceinline__ void cp16(uint32_t d, const void* s) {
    asm volatile("cp.async.cg.shared.global [%0], [%1], 16;" :: "r"(d), "l"(s));
}
#define CP_COMMIT() asm volatile("cp.async.commit_group;" ::: "memory")
#define CP_WAIT0()  asm volatile("cp.async.wait_group 0;" ::: "memory")
#define CP_WAIT1()  asm volatile("cp.async.wait_group 1;" ::: "memory")

// grid.z selects tensor; all same element count n4 (in float4 units)
__global__ void conv_hilo3(const float* __restrict__ a, const float* __restrict__ b,
                           const float* __restrict__ c,
                           __nv_bfloat16* __restrict__ hi, __nv_bfloat16* __restrict__ lo, int n4)
{
    int i = blockIdx.x * blockDim.x + threadIdx.x;
    if (i >= n4) return;
    const float* in = (blockIdx.z == 0) ? a : (blockIdx.z == 1) ? b : c;
    size_t off = (size_t)blockIdx.z * n4 + i;
    float4 v = ((const float4*)in)[i];
    uint32_t h01 = pack_bf16(v.x, v.y), h23 = pack_bf16(v.z, v.w);
    __nv_bfloat162 x = *(__nv_bfloat162*)&h01, y = *(__nv_bfloat162*)&h23;
    ((uint32_t*)hi)[2 * off] = h01; ((uint32_t*)hi)[2 * off + 1] = h23;
    ((uint32_t*)lo)[2 * off]     = pack_bf16(v.x - __bfloat162float(x.x), v.y - __bfloat162float(x.y));
    ((uint32_t*)lo)[2 * off + 1] = pack_bf16(v.z - __bfloat162float(y.x), v.w - __bfloat162float(y.y));
}
__global__ void conv_hilo2(const float* __restrict__ a, const float* __restrict__ b,
                           __nv_bfloat16* __restrict__ hi, __nv_bfloat16* __restrict__ lo, int n4)
{
    int i = blockIdx.x * blockDim.x + threadIdx.x;
    if (i >= n4) return;
    const float* in = (blockIdx.z == 0) ? a : b;
    size_t off = (size_t)blockIdx.z * n4 + i;
    float4 v = ((const float4*)in)[i];
    uint32_t h01 = pack_bf16(v.x, v.y), h23 = pack_bf16(v.z, v.w);
    __nv_bfloat162 x = *(__nv_bfloat162*)&h01, y = *(__nv_bfloat162*)&h23;
    ((uint32_t*)hi)[2 * off] = h01; ((uint32_t*)hi)[2 * off + 1] = h23;
    ((uint32_t*)lo)[2 * off]     = pack_bf16(v.x - __bfloat162float(x.x), v.y - __bfloat162float(x.y));
    ((uint32_t*)lo)[2 * off + 1] = pack_bf16(v.z - __bfloat162float(y.x), v.w - __bfloat162float(y.y));
}

// ---------------------------------------------------------------------------
// Projection GEMM core (R8 version): cp.async 2-stage pipeline, 128x128 tile.
// ---------------------------------------------------------------------------
#define PM 5120
#define PSTG (4 * PM)
#define PROJ_SMEM (2 * PSTG * 2)

__device__ __forceinline__ void proj_stage_load(
    __nv_bfloat16* st, const __nv_bfloat16* Xh, const __nv_bfloat16* Xl,
    const __nv_bfloat16* Wh, const __nv_bfloat16* Wl,
    int m0, int n0, int k0, int tid)
{
    #pragma unroll
    for (int i = 0; i < 2; i++) {
        int idx = tid + i * 256;
        int r = idx >> 2, c8 = (idx & 3) * 8;
        size_t xs = (size_t)(m0 + r) * DMODEL + k0 + c8;
        size_t ws = (size_t)(n0 + r) * DMODEL + k0 + c8;
        uint32_t base = smem_u32(st + r * 40 + c8);
        cp16(base,               Xh + xs);
        cp16(base + PM * 2,      Xl + xs);
        cp16(base + 2 * PM * 2,  Wh + ws);
        cp16(base + 3 * PM * 2,  Wl + ws);
    }
    CP_COMMIT();
}

__device__ __forceinline__ void proj_gemm(
    float acc[2][8][4], __nv_bfloat16* sm,
    const __nv_bfloat16* Xh, const __nv_bfloat16* Xl,
    const __nv_bfloat16* Wh, const __nv_bfloat16* Wl,
    int m0, int n0, int tid, int wm, int wn, int lid)
{
    proj_stage_load(sm, Xh, Xl, Wh, Wl, m0, n0, 0, tid);
    for (int t = 0; t < DMODEL / 32; t++) {
        CP_WAIT0();
        __syncthreads();
        if (t + 1 < DMODEL / 32)
            proj_stage_load(sm + ((t + 1) & 1) * PSTG, Xh, Xl, Wh, Wl, m0, n0, (t + 1) * 32, tid);
        __nv_bfloat16* Ahs = sm + (t & 1) * PSTG;
        __nv_bfloat16* Als = Ahs + PM;
        __nv_bfloat16* Bhs = Ahs + 2 * PM;
        __nv_bfloat16* Bls = Ahs + 3 * PM;
        #pragma unroll
        for (int ks = 0; ks < 32; ks += 16) {
            const int ac = ks + ((lid >> 4) << 3);
            uint32_t ah[2][4], al[2][4], bh[8][2], bl[8][2], r4[4];
            #pragma unroll
            for (int jp = 0; jp < 4; jp++) {
                int rB = 64 * wn + 16 * jp + (lid & 15);
                ldsm4(r4, smem_u32(Bhs + rB * 40 + ac));
                bh[2*jp][0]=r4[0]; bh[2*jp][1]=r4[2]; bh[2*jp+1][0]=r4[1]; bh[2*jp+1][1]=r4[3];
                ldsm4(r4, smem_u32(Bls + rB * 40 + ac));
                bl[2*jp][0]=r4[0]; bl[2*jp][1]=r4[2]; bl[2*jp+1][0]=r4[1]; bl[2*jp+1][1]=r4[3];
            }
            #pragma unroll
            for (int i = 0; i < 2; i++) {
                int rA = 32 * wm + 16 * i + (lid & 15);
                ldsm4(ah[i], smem_u32(Ahs + rA * 40 + ac));
                ldsm4(al[i], smem_u32(Als + rA * 40 + ac));
            }
            #pragma unroll
            for (int i = 0; i < 2; i++)
                #pragma unroll
                for (int j = 0; j < 8; j++) {
                    mma16816(acc[i][j], ah[i], bh[j]);
                    mma16816(acc[i][j], ah[i], bl[j]);
                    mma16816(acc[i][j], al[i], bh[j]);
                }
        }
        __syncthreads();
    }
}

__global__ void __launch_bounds__(256) qkv_proj(
    const __nv_bfloat16* __restrict__ xh, const __nv_bfloat16* __restrict__ xl,
    const __nv_bfloat16* __restrict__ Wh, const __nv_bfloat16* __restrict__ Wl,
    const float* __restrict__ bias,
    __nv_bfloat16* __restrict__ Qh, __nv_bfloat16* __restrict__ Ql,
    __nv_bfloat16* __restrict__ Kh, __nv_bfloat16* __restrict__ Kl,
    __nv_bfloat16* __restrict__ Vh, __nv_bfloat16* __restrict__ Vl)
{
    extern __shared__ __nv_bfloat16 sm[];
    const int tid = threadIdx.x, w = tid >> 5, lid = tid & 31;
    const int wm = w >> 1, wn = w & 1;
    const int m0 = blockIdx.y * 128, n0 = blockIdx.x * 128, z = blockIdx.z;
    const __nv_bfloat16* Xh = xh + (size_t)z * XN;
    const __nv_bfloat16* Xl = xl + (size_t)z * XN;
    __nv_bfloat16* Yh = (z == 0) ? Qh : (z == 1) ? Kh : Vh;
    __nv_bfloat16* Yl = (z == 0) ? Ql : (z == 1) ? Kl : Vl;
    const float sc = (z == 0) ? 0.18033688011112042f : 1.0f;  // 0.125*log2(e)

    float acc[2][8][4] = {};
    proj_gemm(acc, sm, Xh, Xl, Wh, Wl, m0, n0, tid, wm, wn, lid);

    #pragma unroll
    for (int i = 0; i < 2; i++) {
        int r = m0 + 32 * wm + 16 * i + (lid >> 2);
        #pragma unroll
        for (int j = 0; j < 8; j++) {
            int ng = n0 + 64 * wn + 8 * j + (lid & 3) * 2;
            float b0 = bias[ng], b1 = bias[ng + 1];
            int head = ng >> 6;
            #pragma unroll
            for (int hrow = 0; hrow < 2; hrow++) {
                int rr = r + hrow * 8;
                float f0 = (acc[i][j][2*hrow]   + b0) * sc;
                float f1 = (acc[i][j][2*hrow+1] + b1) * sc;
                uint32_t hp = pack_bf16(f0, f1);
                __nv_bfloat162 u = *(__nv_bfloat162*)&hp;
                size_t dst = ((size_t)head * S_LEN + rr) * DK + (ng & 63);
                *(uint32_t*)(Yh + dst) = hp;
                *(uint32_t*)(Yl + dst) = pack_bf16(f0 - __bfloat162float(u.x),
                                                   f1 - __bfloat162float(u.y));
            }
        }
    }
}

__global__ void __launch_bounds__(256) out_proj(
    const __nv_bfloat16* __restrict__ Xh, const __nv_bfloat16* __restrict__ Xl,
    const __nv_bfloat16* __restrict__ Wh, const __nv_bfloat16* __restrict__ Wl,
    const float* __restrict__ bias, float* __restrict__ Yf)
{
    extern __shared__ __nv_bfloat16 sm[];
    const int tid = threadIdx.x, w = tid >> 5, lid = tid & 31;
    const int wm = w >> 1, wn = w & 1;
    const int m0 = blockIdx.y * 128, n0 = blockIdx.x * 128;

    float acc[2][8][4] = {};
    proj_gemm(acc, sm, Xh, Xl, Wh, Wl, m0, n0, tid, wm, wn, lid);

    #pragma unroll
    for (int i = 0; i < 2; i++) {
        int r = m0 + 32 * wm + 16 * i + (lid >> 2);
        #pragma unroll
        for (int j = 0; j < 8; j++) {
            int ng = n0 + 64 * wn + 8 * j + (lid & 3) * 2;
            float b0 = bias[ng], b1 = bias[ng + 1];
            #pragma unroll
            for (int hrow = 0; hrow < 2; hrow++) {
                int rr = r + hrow * 8;
                Yf[(size_t)rr * DMODEL + ng]     = acc[i][j][2*hrow]   + b0;
                Yf[(size_t)rr * DMODEL + ng + 1] = acc[i][j][2*hrow+1] + b1;
            }
        }
    }
}

// ---------------------------------------------------------------------------
// Flash attention: CTA = (head, 128 q rows), 8 warps x 16 rows, Bc=64.
// 3-stage cp.async KV pipeline; Q fragments hoisted to registers.
// ---------------------------------------------------------------------------
#define QS 72
#define NT (S_LEN / 64)
#define AT_SMEM ((256 + 3 * 256) * QS * 2)   // Q hi/lo + 3 KV stages (144KB)

__device__ __forceinline__ void attn_stage_load(
    __nv_bfloat16 (*SN)[QS], const __nv_bfloat16* Kh, const __nv_bfloat16* Kl,
    const __nv_bfloat16* Vh, const __nv_bfloat16* Vl,
    const __nv_bfloat16* /*unused*/, size_t hbase, int kv0, int tid)
{
    #pragma unroll
    for (int i = 0; i < 2; i++) {
        int idx = tid + i * 256;
        int r = idx >> 3, c8 = (idx & 7) * 8;
        size_t src = hbase + (size_t)(kv0 + r) * DK + c8;
        cp16(smem_u32(&SN[r][c8]),       Kh + src);
        cp16(smem_u32(&SN[64 + r][c8]),  Kl + src);
        cp16(smem_u32(&SN[128 + r][c8]), Vh + src);
        cp16(smem_u32(&SN[192 + r][c8]), Vl + src);
    }
    CP_COMMIT();
}

__global__ void __launch_bounds__(256, 1) attn_tc(
    const __nv_bfloat16* __restrict__ Qh, const __nv_bfloat16* __restrict__ Ql,
    const __nv_bfloat16* __restrict__ Kh, const __nv_bfloat16* __restrict__ Kl,
    const __nv_bfloat16* __restrict__ Vh, const __nv_bfloat16* __restrict__ Vl,
    __nv_bfloat16* __restrict__ Ah, __nv_bfloat16* __restrict__ Al)
{
    extern __shared__ __nv_bfloat16 sm[];
    __nv_bfloat16 (*Qhs)[QS] = (__nv_bfloat16(*)[QS])sm;   // 128 rows
    __nv_bfloat16 (*Qls)[QS] = Qhs + 128;
    __nv_bfloat16 (*KV0)[QS] = Qls + 128;                   // 3 stages x 256 rows

    const int tid = threadIdx.x, w = tid >> 5, lid = tid & 31;
    const int h = blockIdx.y, q0 = blockIdx.x * 128;
    const size_t hbase = (size_t)h * S_LEN * DK;

    #pragma unroll
    for (int i = 0; i < 4; i++) {              // Q: 1024 uint4
        int idx = tid + i * 256;
        int r = idx >> 3, c8 = (idx & 7) * 8;
        size_t src = hbase + (size_t)(q0 + r) * DK + c8;
        *(uint4*)&Qhs[r][c8] = *(const uint4*)(Qh + src);
        *(uint4*)&Qls[r][c8] = *(const uint4*)(Ql + src);
    }
    attn_stage_load(KV0,       Kh, Kl, Vh, Vl, 0, hbase, 0,  tid);
    attn_stage_load(KV0 + 256, Kh, Kl, Vh, Vl, 0, hbase, 64, tid);
    __syncthreads();                            // Q resident for fragment hoist

    // hoist Q fragments (hi+lo) into registers once
    uint32_t qhf[4][4], qlf[4][4];
    #pragma unroll
    for (int ks = 0; ks < 4; ks++) {
        const int ac = 16 * ks + ((lid >> 4) << 3);
        ldsm4(qhf[ks], smem_u32(&Qhs[16 * w + (lid & 15)][ac]));
        ldsm4(qlf[ks], smem_u32(&Qls[16 * w + (lid & 15)][ac]));
    }

    float O[8][4] = {};
    float m0r = -INFINITY, m1r = -INFINITY, l0r = 0.f, l1r = 0.f;

    for (int t = 0; t < NT; t++) {
        if (t == NT - 1) { CP_WAIT0(); } else { CP_WAIT1(); }
        __syncthreads();                        // stage t%3 resident
        if (t + 2 < NT)
            attn_stage_load(KV0 + ((t + 2) % 3) * 256, Kh, Kl, Vh, Vl, 0, hbase, (t + 2) * 64, tid);

        __nv_bfloat16 (*Khs)[QS] = KV0 + (t % 3) * 256;
        __nv_bfloat16 (*Kls)[QS] = Khs + 64;
        __nv_bfloat16 (*Vhs)[QS] = Khs + 128;
        __nv_bfloat16 (*Vls)[QS] = Khs + 192;

        // S = Q K^T
        float s[8][4] = {};
        #pragma unroll
        for (int ks = 0; ks < 4; ks++) {
            const int ac = 16 * ks + ((lid >> 4) << 3);
            uint32_t bh[8][2], bl[8][2], r4[4];
            #pragma unroll
            for (int jp = 0; jp < 4; jp++) {
                int rB = 16 * jp + (lid & 15);
                ldsm4(r4, smem_u32(&Khs[rB][ac]));
                bh[2*jp][0]=r4[0]; bh[2*jp][1]=r4[2]; bh[2*jp+1][0]=r4[1]; bh[2*jp+1][1]=r4[3];
                ldsm4(r4, smem_u32(&Kls[rB][ac]));
                bl[2*jp][0]=r4[0]; bl[2*jp][1]=r4[2]; bl[2*jp+1][0]=r4[1]; bl[2*jp+1][1]=r4[3];
            }
            #pragma unroll
            for (int j = 0; j < 8; j++) {
                mma16816(s[j], qhf[ks], bh[j]);
                mma16816(s[j], qhf[ks], bl[j]);
                mma16816(s[j], qlf[ks], bh[j]);
            }
        }

        // online softmax (log2 domain; scale folded into Q)
        float rm0 = -INFINITY, rm1 = -INFINITY;
        #pragma unroll
        for (int j = 0; j < 8; j++) {
            rm0 = fmaxf(rm0, fmaxf(s[j][0], s[j][1]));
            rm1 = fmaxf(rm1, fmaxf(s[j][2], s[j][3]));
        }
        rm0 = fmaxf(rm0, __shfl_xor_sync(~0u, rm0, 1)); rm0 = fmaxf(rm0, __shfl_xor_sync(~0u, rm0, 2));
        rm1 = fmaxf(rm1, __shfl_xor_sync(~0u, rm1, 1)); rm1 = fmaxf(rm1, __shfl_xor_sync(~0u, rm1, 2));
        float mn0 = fmaxf(m0r, rm0), mn1 = fmaxf(m1r, rm1);
        float c0 = ex2f(m0r - mn0), c1 = ex2f(m1r - mn1);
        m0r = mn0; m1r = mn1;
        float s0 = 0.f, s1 = 0.f;
        #pragma unroll
        for (int j = 0; j < 8; j++) {
            s[j][0] = ex2f(s[j][0] - mn0); s[j][1] = ex2f(s[j][1] - mn0);
            s[j][2] = ex2f(s[j][2] - mn1); s[j][3] = ex2f(s[j][3] - mn1);
            s0 += s[j][0] + s[j][1]; s1 += s[j][2] + s[j][3];
        }
        s0 += __shfl_xor_sync(~0u, s0, 1); s0 += __shfl_xor_sync(~0u, s0, 2);
        s1 += __shfl_xor_sync(~0u, s1, 1); s1 += __shfl_xor_sync(~0u, s1, 2);
        l0r = l0r * c0 + s0; l1r = l1r * c1 + s1;
        #pragma unroll
        for (int j = 0; j < 8; j++) { O[j][0] *= c0; O[j][1] *= c0; O[j][2] *= c1; O[j][3] *= c1; }

        // P -> bf16 hi/lo A-fragments
        uint32_t ph[4][4], pl[4][4];
        #pragma unroll
        for (int j2 = 0; j2 < 4; j2++) {
            int t0 = 2 * j2, t1 = t0 + 1;
            ph[j2][0] = pack_bf16(s[t0][0], s[t0][1]); ph[j2][1] = pack_bf16(s[t0][2], s[t0][3]);
            ph[j2][2] = pack_bf16(s[t1][0], s[t1][1]); ph[j2][3] = pack_bf16(s[t1][2], s[t1][3]);
            #pragma unroll
            for (int q = 0; q < 4; q++) {
                __nv_bfloat162 u = *(__nv_bfloat162*)&ph[j2][q];
                const float* sv = (q < 2) ? s[t0] : s[t1];
                int b = (q & 1) * 2;
                pl[j2][q] = pack_bf16(sv[b] - __bfloat162float(u.x),
                                      sv[b + 1] - __bfloat162float(u.y));
            }
        }

        // O += P V
        #pragma unroll
        for (int j2 = 0; j2 < 4; j2++) {
            uint32_t vh[8][2], vl[8][2], r4[4];
            #pragma unroll
            for (int np = 0; np < 4; np++) {
                int rV = 16 * j2 + (lid & 15), cV = 16 * np + ((lid >> 4) << 3);
                ldsm4t(r4, smem_u32(&Vhs[rV][cV]));
                vh[2*np][0]=r4[0]; vh[2*np][1]=r4[1]; vh[2*np+1][0]=r4[2]; vh[2*np+1][1]=r4[3];
                ldsm4t(r4, smem_u32(&Vls[rV][cV]));
                vl[2*np][0]=r4[0]; vl[2*np][1]=r4[1]; vl[2*np+1][0]=r4[2]; vl[2*np+1][1]=r4[3];
            }
            #pragma unroll
            for (int tt = 0; tt < 8; tt++) {
                mma16816(O[tt], ph[j2], vh[tt]);
                mma16816(O[tt], ph[j2], vl[tt]);
                mma16816(O[tt], pl[j2], vh[tt]);
            }
        }
    }

    float i0 = 1.f / l0r, i1 = 1.f / l1r;
    #pragma unroll
    for (int t = 0; t < 8; t++) {
        int c = h * DK + 8 * t + (lid & 3) * 2;
        int r0 = q0 + 16 * w + (lid >> 2);
        #pragma unroll
        for (int hrow = 0; hrow < 2; hrow++) {
            float f0 = O[t][2*hrow]   * (hrow ? i1 : i0);
            float f1 = O[t][2*hrow+1] * (hrow ? i1 : i0);
            uint32_t hp = pack_bf16(f0, f1);
            __nv_bfloat162 u = *(__nv_bfloat162*)&hp;
            size_t dst = (size_t)(r0 + hrow * 8) * DMODEL + c;
            *(uint32_t*)(Ah + dst) = hp;
            *(uint32_t*)(Al + dst) = pack_bf16(f0 - __bfloat162float(u.x),
                                               f1 - __bfloat162float(u.y));
        }
    }
}

extern "C" void kernel_launch(void* const* d_in, const int* in_sizes, int n_in,
                              void* d_out, int out_size)
{
    const float* q  = (const float*)d_in[0];
    const float* k  = (const float*)d_in[1];
    const float* v  = (const float*)d_in[2];
    const float* Wq = (const float*)d_in[3];
    const float* bq = (const float*)d_in[4];
    const float* Wo = (const float*)d_in[5];
    const float* bo = (const float*)d_in[6];
    float* out = (float*)d_out;

    __nv_bfloat16 *xh, *xl, *wh, *wl, *qh, *ql, *kh, *kl, *vh, *vl, *ah, *al;
    cudaGetSymbolAddress((void**)&xh, g_xh); cudaGetSymbolAddress((void**)&xl, g_xl);
    cudaGetSymbolAddress((void**)&wh, g_wh); cudaGetSymbolAddress((void**)&wl, g_wl);
    cudaGetSymbolAddress((void**)&qh, g_qh); cudaGetSymbolAddress((void**)&ql, g_ql);
    cudaGetSymbolAddress((void**)&kh, g_kh); cudaGetSymbolAddress((void**)&kl, g_kl);
    cudaGetSymbolAddress((void**)&vh, g_vh); cudaGetSymbolAddress((void**)&vl, g_vl);
    cudaGetSymbolAddress((void**)&ah, g_ah); cudaGetSymbolAddress((void**)&al, g_al);

    cudaFuncSetAttribute(attn_tc,  cudaFuncAttributeMaxDynamicSharedMemorySize, AT_SMEM);
    cudaFuncSetAttribute(qkv_proj, cudaFuncAttributeMaxDynamicSharedMemorySize, PROJ_SMEM);
    cudaFuncSetAttribute(out_proj, cudaFuncAttributeMaxDynamicSharedMemorySize, PROJ_SMEM);

    dim3 gc3(XN / 4 / 256, 1, 3);
    conv_hilo3<<<gc3, 256>>>(q, k, v, xh, xl, XN / 4);
    dim3 gc2(WN / 4 / 256, 1, 2);
    conv_hilo2<<<gc2, 256>>>(Wq, Wo, wh, wl, WN / 4);

    dim3 gqkv(DMODEL / 128, S_LEN / 128, 3);   // 6 x 32 x 3
    qkv_proj<<<gqkv, 256, PROJ_SMEM>>>(xh, xl, wh, wl, bq, qh, ql, kh, kl, vh, vl);

    dim3 gattn(S_LEN / 128, NH);               // 32 x 12
    attn_tc<<<gattn, 256, AT_SMEM>>>(qh, ql, kh, kl, vh, vl, ah, al);

    dim3 gout(DMODEL / 128, S_LEN / 128);      // 6 x 32
    out_proj<<<gout, 256, PROJ_SMEM>>>(ah, al, wh + WN, wl + WN, bo, out);
}

// round 11
// speedup vs baseline: 1.2911x; 1.2367x over previous
#include <cuda_runtime.h>
#include <cuda_fp16.h>
#include <math.h>
#include <stdint.h>

#define S_LEN 4096
#define DMODEL 768
#define NH 12
#define DK 64
#define XN (S_LEN * DMODEL)
#define WN (DMODEL * DMODEL)

__device__ __half g_xh[3 * XN], g_xl[3 * XN];
__device__ __half g_wh[2 * WN], g_wl[2 * WN];
__device__ __half g_qh[XN], g_ql[XN], g_kh[XN], g_kl[XN], g_vh[XN], g_vl[XN];
__device__ __half g_ah[XN], g_al[XN];

__device__ __forceinline__ uint32_t smem_u32(const void* p) {
    uint32_t a;
    asm("{ .reg .u64 t; cvta.to.shared.u64 t, %1; cvt.u32.u64 %0, t; }" : "=r"(a) : "l"(p));
    return a;
}
__device__ __forceinline__ float ex2f(float x) {
    float r; asm("ex2.approx.ftz.f32 %0, %1;" : "=f"(r) : "f"(x)); return r;
}
__device__ __forceinline__ uint32_t pack_f16(float a, float b) {  // low=a, high=b
    __half2 h = __floats2half2_rn(a, b);
    return *(uint32_t*)&h;
}
__device__ __forceinline__ void ldsm4(uint32_t* r, uint32_t a) {
    asm volatile("ldmatrix.sync.aligned.m8n8.x4.shared.b16 {%0,%1,%2,%3}, [%4];"
                 : "=r"(r[0]), "=r"(r[1]), "=r"(r[2]), "=r"(r[3]) : "r"(a));
}
__device__ __forceinline__ void ldsm4t(uint32_t* r, uint32_t a) {
    asm volatile("ldmatrix.sync.aligned.m8n8.x4.trans.shared.b16 {%0,%1,%2,%3}, [%4];"
                 : "=r"(r[0]), "=r"(r[1]), "=r"(r[2]), "=r"(r[3]) : "r"(a));
}
__device__ __forceinline__ void mma16816(float* d, const uint32_t* a, const uint32_t* b) {
    asm volatile("mma.sync.aligned.m16n8k16.row.col.f32.f16.f16.f32 "
                 "{%0,%1,%2,%3}, {%4,%5,%6,%7}, {%8,%9}, {%0,%1,%2,%3};"
                 : "+f"(d[0]), "+f"(d[1]), "+f"(d[2]), "+f"(d[3])
                 : "r"(a[0]), "r"(a[1]), "r"(a[2]), "r"(a[3]), "r"(b[0]), "r"(b[1]));
}
__device__ __forceinline__ void cp16(uint32_t d, const void* s) {
    asm volatile("cp.async.cg.shared.global [%0], [%1], 16;" :: "r"(d), "l"(s));
}
#define CP_COMMIT() asm volatile("cp.async.commit_group;" ::: "memory")
#define CP_WAIT0()  asm volatile("cp.async.wait_group 0;" ::: "memory")
#define CP_WAIT1()  asm volatile("cp.async.wait_group 1;" ::: "memory")

__global__ void conv_hilo3(const float* __restrict__ a, const float* __restrict__ b,
                           const float* __restrict__ c,
                           __half* __restrict__ hi, __half* __restrict__ lo, int n4)
{
    int i = blockIdx.x * blockDim.x + threadIdx.x;
    if (i >= n4) return;
    const float* in = (blockIdx.z == 0) ? a : (blockIdx.z == 1) ? b : c;
    size_t off = (size_t)blockIdx.z * n4 + i;
    float4 v = ((const float4*)in)[i];
    __half2 h01 = __floats2half2_rn(v.x, v.y), h23 = __floats2half2_rn(v.z, v.w);
    ((__half2*)hi)[2 * off] = h01; ((__half2*)hi)[2 * off + 1] = h23;
    ((__half2*)lo)[2 * off]     = __floats2half2_rn(v.x - __half2float(h01.x), v.y - __half2float(h01.y));
    ((__half2*)lo)[2 * off + 1] = __floats2half2_rn(v.z - __half2float(h23.x), v.w - __half2float(h23.y));
}
__global__ void conv_hilo2(const float* __restrict__ a, const float* __restrict__ b,
                           __half* __restrict__ hi, __half* __restrict__ lo, int n4)
{
    int i = blockIdx.x * blockDim.x + threadIdx.x;
    if (i >= n4) return;
    const float* in = (blockIdx.z == 0) ? a : b;
    size_t off = (size_t)blockIdx.z * n4 + i;
    float4 v = ((const float4*)in)[i];
    __half2 h01 = __floats2half2_rn(v.x, v.y), h23 = __floats2half2_rn(v.z, v.w);
    ((__half2*)hi)[2 * off] = h01; ((__half2*)hi)[2 * off + 1] = h23;
    ((__half2*)lo)[2 * off]     = __floats2half2_rn(v.x - __half2float(h01.x), v.y - __half2float(h01.y));
    ((__half2*)lo)[2 * off + 1] = __floats2half2_rn(v.z - __half2float(h23.x), v.w - __half2float(h23.y));
}

// ---------------------------------------------------------------------------
// Projection GEMM core: fp16 hi/lo, 3-pass, cp.async 2-stage, 128x128 tile.
// ---------------------------------------------------------------------------
#define PM 5120
#define PSTG (4 * PM)
#define PROJ_SMEM (2 * PSTG * 2)

__device__ __forceinline__ void proj_stage_load(
    __half* st, const __half* Xh, const __half* Xl,
    const __half* Wh, const __half* Wl, int m0, int n0, int k0, int tid)
{
    #pragma unroll
    for (int i = 0; i < 2; i++) {
        int idx = tid + i * 256;
        int r = idx >> 2, c8 = (idx & 3) * 8;
        size_t xs = (size_t)(m0 + r) * DMODEL + k0 + c8;
        size_t ws = (size_t)(n0 + r) * DMODEL + k0 + c8;
        uint32_t base = smem_u32(st + r * 40 + c8);
        cp16(base,               Xh + xs);
        cp16(base + PM * 2,      Xl + xs);
        cp16(base + 2 * PM * 2,  Wh + ws);
        cp16(base + 3 * PM * 2,  Wl + ws);
    }
    CP_COMMIT();
}

__device__ __forceinline__ void proj_gemm(
    float acc[2][8][4], __half* sm,
    const __half* Xh, const __half* Xl, const __half* Wh, const __half* Wl,
    int m0, int n0, int tid, int wm, int wn, int lid)
{
    proj_stage_load(sm, Xh, Xl, Wh, Wl, m0, n0, 0, tid);
    for (int t = 0; t < DMODEL / 32; t++) {
        CP_WAIT0();
        __syncthreads();
        if (t + 1 < DMODEL / 32)
            proj_stage_load(sm + ((t + 1) & 1) * PSTG, Xh, Xl, Wh, Wl, m0, n0, (t + 1) * 32, tid);
        __half* Ahs = sm + (t & 1) * PSTG;
        __half* Als = Ahs + PM;
        __half* Bhs = Ahs + 2 * PM;
        __half* Bls = Ahs + 3 * PM;
        #pragma unroll
        for (int ks = 0; ks < 32; ks += 16) {
            const int ac = ks + ((lid >> 4) << 3);
            uint32_t ah[2][4], al[2][4], bh[8][2], bl[8][2], r4[4];
            #pragma unroll
            for (int jp = 0; jp < 4; jp++) {
                int rB = 64 * wn + 16 * jp + (lid & 15);
                ldsm4(r4, smem_u32(Bhs + rB * 40 + ac));
                bh[2*jp][0]=r4[0]; bh[2*jp][1]=r4[2]; bh[2*jp+1][0]=r4[1]; bh[2*jp+1][1]=r4[3];
                ldsm4(r4, smem_u32(Bls + rB * 40 + ac));
                bl[2*jp][0]=r4[0]; bl[2*jp][1]=r4[2]; bl[2*jp+1][0]=r4[1]; bl[2*jp+1][1]=r4[3];
            }
            #pragma unroll
            for (int i = 0; i < 2; i++) {
                int rA = 32 * wm + 16 * i + (lid & 15);
                ldsm4(ah[i], smem_u32(Ahs + rA * 40 + ac));
                ldsm4(al[i], smem_u32(Als + rA * 40 + ac));
            }
            #pragma unroll
            for (int i = 0; i < 2; i++) {
                #pragma unroll
                for (int j = 0; j < 8; j++) mma16816(acc[i][j], ah[i], bh[j]);
                #pragma unroll
                for (int j = 0; j < 8; j++) mma16816(acc[i][j], ah[i], bl[j]);
                #pragma unroll
                for (int j = 0; j < 8; j++) mma16816(acc[i][j], al[i], bh[j]);
            }
        }
        __syncthreads();
    }
}

__global__ void __launch_bounds__(256) qkv_proj(
    const __half* __restrict__ xh, const __half* __restrict__ xl,
    const __half* __restrict__ Wh, const __half* __restrict__ Wl,
    const float* __restrict__ bias,
    __half* __restrict__ Qh, __half* __restrict__ Ql,
    __half* __restrict__ Kh, __half* __restrict__ Kl,
    __half* __restrict__ Vh, __half* __restrict__ Vl)
{
    extern __shared__ __half sm[];
    const int tid = threadIdx.x, w = tid >> 5, lid = tid & 31;
    const int wm = w >> 1, wn = w & 1;
    const int m0 = blockIdx.y * 128, n0 = blockIdx.x * 128, z = blockIdx.z;
    const __half* Xh = xh + (size_t)z * XN;
    const __half* Xl = xl + (size_t)z * XN;
    __half* Yh = (z == 0) ? Qh : (z == 1) ? Kh : Vh;
    __half* Yl = (z == 0) ? Ql : (z == 1) ? Kl : Vl;
    const float sc = (z == 0) ? 0.18033688011112042f : 1.0f;  // 0.125*log2(e)

    float acc[2][8][4] = {};
    proj_gemm(acc, sm, Xh, Xl, Wh, Wl, m0, n0, tid, wm, wn, lid);

    #pragma unroll
    for (int i = 0; i < 2; i++) {
        int r = m0 + 32 * wm + 16 * i + (lid >> 2);
        #pragma unroll
        for (int j = 0; j < 8; j++) {
            int ng = n0 + 64 * wn + 8 * j + (lid & 3) * 2;
            float b0 = bias[ng], b1 = bias[ng + 1];
            int head = ng >> 6;
            #pragma unroll
            for (int hrow = 0; hrow < 2; hrow++) {
                int rr = r + hrow * 8;
                float f0 = (acc[i][j][2*hrow]   + b0) * sc;
                float f1 = (acc[i][j][2*hrow+1] + b1) * sc;
                uint32_t hp = pack_f16(f0, f1);
                __half2 u = *(__half2*)&hp;
                size_t dst = ((size_t)head * S_LEN + rr) * DK + (ng & 63);
                *(uint32_t*)(Yh + dst) = hp;
                *(uint32_t*)(Yl + dst) = pack_f16(f0 - __half2float(u.x),
                                                  f1 - __half2float(u.y));
            }
        }
    }
}

__global__ void __launch_bounds__(256) out_proj(
    const __half* __restrict__ Xh, const __half* __restrict__ Xl,
    const __half* __restrict__ Wh, const __half* __restrict__ Wl,
    const float* __restrict__ bias, float* __restrict__ Yf)
{
    extern __shared__ __half sm[];
    const int tid = threadIdx.x, w = tid >> 5, lid = tid & 31;
    const int wm = w >> 1, wn = w & 1;
    const int m0 = blockIdx.y * 128, n0 = blockIdx.x * 128;

    float acc[2][8][4] = {};
    proj_gemm(acc, sm, Xh, Xl, Wh, Wl, m0, n0, tid, wm, wn, lid);

    #pragma unroll
    for (int i = 0; i < 2; i++) {
        int r = m0 + 32 * wm + 16 * i + (lid >> 2);
        #pragma unroll
        for (int j = 0; j < 8; j++) {
            int ng = n0 + 64 * wn + 8 * j + (lid & 3) * 2;
            float b0 = bias[ng], b1 = bias[ng + 1];
            #pragma unroll
            for (int hrow = 0; hrow < 2; hrow++) {
                int rr = r + hrow * 8;
                Yf[(size_t)rr * DMODEL + ng]     = acc[i][j][2*hrow]   + b0;
                Yf[(size_t)rr * DMODEL + ng + 1] = acc[i][j][2*hrow+1] + b1;
            }
        }
    }
}

// ---------------------------------------------------------------------------
// Flash attention: CTA=(head, 128 q rows), 8 warps, Bc=64, fp16 2-pass.
// S = (Qh+Ql)·Kh (no Kl needed); O = Ph·(Vh+Vl) (no Pl needed).
// 3-stage cp.async pipeline of [Kh|Vh|Vl]; Q fragments hoisted.
// ---------------------------------------------------------------------------
#define QS 72
#define NT (S_LEN / 64)
#define AT_SMEM ((256 + 3 * 192) * QS * 2)   // ~117KB

__device__ __forceinline__ void attn_stage_load(
    __half (*SN)[QS], const __half* Kh, const __half* Vh, const __half* Vl,
    size_t hbase, int kv0, int tid)
{
    #pragma unroll
    for (int i = 0; i < 2; i++) {
        int idx = tid + i * 256;
        int r = idx >> 3, c8 = (idx & 7) * 8;
        size_t src = hbase + (size_t)(kv0 + r) * DK + c8;
        cp16(smem_u32(&SN[r][c8]),       Kh + src);
        cp16(smem_u32(&SN[64 + r][c8]),  Vh + src);
        cp16(smem_u32(&SN[128 + r][c8]), Vl + src);
    }
    CP_COMMIT();
}

__global__ void __launch_bounds__(256, 1) attn_tc(
    const __half* __restrict__ Qh, const __half* __restrict__ Ql,
    const __half* __restrict__ Kh, const __half* __restrict__ Kl,
    const __half* __restrict__ Vh, const __half* __restrict__ Vl,
    __half* __restrict__ Ah, __half* __restrict__ Al)
{
    extern __shared__ __half sm[];
    __half (*Qhs)[QS] = (__half(*)[QS])sm;      // 128 rows
    __half (*Qls)[QS] = Qhs + 128;
    __half (*KV0)[QS] = Qls + 128;               // 3 stages x 192 rows

    const int tid = threadIdx.x, w = tid >> 5, lid = tid & 31;
    const int h = blockIdx.y, q0 = blockIdx.x * 128;
    const size_t hbase = (size_t)h * S_LEN * DK;

    #pragma unroll
    for (int i = 0; i < 4; i++) {
        int idx = tid + i * 256;
        int r = idx >> 3, c8 = (idx & 7) * 8;
        size_t src = hbase + (size_t)(q0 + r) * DK + c8;
        *(uint4*)&Qhs[r][c8] = *(const uint4*)(Qh + src);
        *(uint4*)&Qls[r][c8] = *(const uint4*)(Ql + src);
    }
    attn_stage_load(KV0,       Kh, Vh, Vl, hbase, 0,  tid);
    attn_stage_load(KV0 + 192, Kh, Vh, Vl, hbase, 64, tid);
    __syncthreads();

    uint32_t qhf[4][4], qlf[4][4];
    #pragma unroll
    for (int ks = 0; ks < 4; ks++) {
        const int ac = 16 * ks + ((lid >> 4) << 3);
        ldsm4(qhf[ks], smem_u32(&Qhs[16 * w + (lid & 15)][ac]));
        ldsm4(qlf[ks], smem_u32(&Qls[16 * w + (lid & 15)][ac]));
    }

    float O[8][4] = {};
    float m0r = -INFINITY, m1r = -INFINITY, l0r = 0.f, l1r = 0.f;

    for (int t = 0; t < NT; t++) {
        if (t == NT - 1) { CP_WAIT0(); } else { CP_WAIT1(); }
        __syncthreads();
        if (t + 2 < NT)
            attn_stage_load(KV0 + ((t + 2) % 3) * 192, Kh, Vh, Vl, hbase, (t + 2) * 64, tid);

        __half (*Khs)[QS] = KV0 + (t % 3) * 192;
        __half (*Vhs)[QS] = Khs + 64;
        __half (*Vls)[QS] = Khs + 128;

        // S = (Qh + Ql) . Kh^T  -- 2 passes
        float s[8][4] = {};
        #pragma unroll
        for (int ks = 0; ks < 4; ks++) {
            const int ac = 16 * ks + ((lid >> 4) << 3);
            uint32_t bh[8][2], r4[4];
            #pragma unroll
            for (int jp = 0; jp < 4; jp++) {
                int rB = 16 * jp + (lid & 15);
                ldsm4(r4, smem_u32(&Khs[rB][ac]));
                bh[2*jp][0]=r4[0]; bh[2*jp][1]=r4[2]; bh[2*jp+1][0]=r4[1]; bh[2*jp+1][1]=r4[3];
            }
            #pragma unroll
            for (int j = 0; j < 8; j++) mma16816(s[j], qhf[ks], bh[j]);
            #pragma unroll
            for (int j = 0; j < 8; j++) mma16816(s[j], qlf[ks], bh[j]);
        }

        // online softmax (log2 domain; scale folded into Q)
        float rm0 = -INFINITY, rm1 = -INFINITY;
        #pragma unroll
        for (int j = 0; j < 8; j++) {
            rm0 = fmaxf(rm0, fmaxf(s[j][0], s[j][1]));
            rm1 = fmaxf(rm1, fmaxf(s[j][2], s[j][3]));
        }
        rm0 = fmaxf(rm0, __shfl_xor_sync(~0u, rm0, 1)); rm0 = fmaxf(rm0, __shfl_xor_sync(~0u, rm0, 2));
        rm1 = fmaxf(rm1, __shfl_xor_sync(~0u, rm1, 1)); rm1 = fmaxf(rm1, __shfl_xor_sync(~0u, rm1, 2));
        float mn0 = fmaxf(m0r, rm0), mn1 = fmaxf(m1r, rm1);
        float c0 = ex2f(m0r - mn0), c1 = ex2f(m1r - mn1);
        m0r = mn0; m1r = mn1;
        float s0 = 0.f, s1 = 0.f;
        #pragma unroll
        for (int j = 0; j < 8; j++) {
            s[j][0] = ex2f(s[j][0] - mn0); s[j][1] = ex2f(s[j][1] - mn0);
            s[j][2] = ex2f(s[j][2] - mn1); s[j][3] = ex2f(s[j][3] - mn1);
            s0 += s[j][0] + s[j][1]; s1 += s[j][2] + s[j][3];
        }
        s0 += __shfl_xor_sync(~0u, s0, 1); s0 += __shfl_xor_sync(~0u, s0, 2);
        s1 += __shfl_xor_sync(~0u, s1, 1); s1 += __shfl_xor_sync(~0u, s1, 2);
        l0r = l0r * c0 + s0; l1r = l1r * c1 + s1;
        #pragma unroll
        for (int j = 0; j < 8; j++) { O[j][0] *= c0; O[j][1] *= c0; O[j][2] *= c1; O[j][3] *= c1; }

        // P -> fp16 A-fragments (hi only)
        uint32_t ph[4][4];
        #pragma unroll
        for (int j2 = 0; j2 < 4; j2++) {
            int t0 = 2 * j2, t1 = t0 + 1;
            ph[j2][0] = pack_f16(s[t0][0], s[t0][1]); ph[j2][1] = pack_f16(s[t0][2], s[t0][3]);
            ph[j2][2] = pack_f16(s[t1][0], s[t1][1]); ph[j2][3] = pack_f16(s[t1][2], s[t1][3]);
        }

        // O += Ph . (Vh + Vl)  -- 2 passes
        #pragma unroll
        for (int j2 = 0; j2 < 4; j2++) {
            uint32_t vh[8][2], vl[8][2], r4[4];
            #pragma unroll
            for (int np = 0; np < 4; np++) {
                int rV = 16 * j2 + (lid & 15), cV = 16 * np + ((lid >> 4) << 3);
                ldsm4t(r4, smem_u32(&Vhs[rV][cV]));
                vh[2*np][0]=r4[0]; vh[2*np][1]=r4[1]; vh[2*np+1][0]=r4[2]; vh[2*np+1][1]=r4[3];
                ldsm4t(r4, smem_u32(&Vls[rV][cV]));
                vl[2*np][0]=r4[0]; vl[2*np][1]=r4[1]; vl[2*np+1][0]=r4[2]; vl[2*np+1][1]=r4[3];
            }
            #pragma unroll
            for (int tt = 0; tt < 8; tt++) mma16816(O[tt], ph[j2], vh[tt]);
            #pragma unroll
            for (int tt = 0; tt < 8; tt++) mma16816(O[tt], ph[j2], vl[tt]);
        }
    }

    float i0 = 1.f / l0r, i1 = 1.f / l1r;
    #pragma unroll
    for (int t = 0; t < 8; t++) {
        int c = h * DK + 8 * t + (lid & 3) * 2;
        int r0 = q0 + 16 * w + (lid >> 2);
        #pragma unroll
        for (int hrow = 0; hrow < 2; hrow++) {
            float f0 = O[t][2*hrow]   * (hrow ? i1 : i0);
            float f1 = O[t][2*hrow+1] * (hrow ? i1 : i0);
            uint32_t hp = pack_f16(f0, f1);
            __half2 u = *(__half2*)&hp;
            size_t dst = (size_t)(r0 + hrow * 8) * DMODEL + c;
            *(uint32_t*)(Ah + dst) = hp;
            *(uint32_t*)(Al + dst) = pack_f16(f0 - __half2float(u.x),
                                              f1 - __half2float(u.y));
        }
    }
}

extern "C" void kernel_launch(void* const* d_in, const int* in_sizes, int n_in,
                              void* d_out, int out_size)
{
    const float* q  = (const float*)d_in[0];
    const float* k  = (const float*)d_in[1];
    const float* v  = (const float*)d_in[2];
    const float* Wq = (const float*)d_in[3];
    const float* bq = (const float*)d_in[4];
    const float* Wo = (const float*)d_in[5];
    const float* bo = (const float*)d_in[6];
    float* out = (float*)d_out;

    __half *xh, *xl, *wh, *wl, *qh, *ql, *kh, *kl, *vh, *vl, *ah, *al;
    cudaGetSymbolAddress((void**)&xh, g_xh); cudaGetSymbolAddress((void**)&xl, g_xl);
    cudaGetSymbolAddress((void**)&wh, g_wh); cudaGetSymbolAddress((void**)&wl, g_wl);
    cudaGetSymbolAddress((void**)&qh, g_qh); cudaGetSymbolAddress((void**)&ql, g_ql);
    cudaGetSymbolAddress((void**)&kh, g_kh); cudaGetSymbolAddress((void**)&kl, g_kl);
    cudaGetSymbolAddress((void**)&vh, g_vh); cudaGetSymbolAddress((void**)&vl, g_vl);
    cudaGetSymbolAddress((void**)&ah, g_ah); cudaGetSymbolAddress((void**)&al, g_al);

    cudaFuncSetAttribute(attn_tc,  cudaFuncAttributeMaxDynamicSharedMemorySize, AT_SMEM);
    cudaFuncSetAttribute(qkv_proj, cudaFuncAttributeMaxDynamicSharedMemorySize, PROJ_SMEM);
    cudaFuncSetAttribute(out_proj, cudaFuncAttributeMaxDynamicSharedMemorySize, PROJ_SMEM);

    dim3 gc3(XN / 4 / 256, 1, 3);
    conv_hilo3<<<gc3, 256>>>(q, k, v, xh, xl, XN / 4);
    dim3 gc2(WN / 4 / 256, 1, 2);
    conv_hilo2<<<gc2, 256>>>(Wq, Wo, wh, wl, WN / 4);

    dim3 gqkv(DMODEL / 128, S_LEN / 128, 3);   // 6 x 32 x 3
    qkv_proj<<<gqkv, 256, PROJ_SMEM>>>(xh, xl, wh, wl, bq, qh, ql, kh, kl, vh, vl);

    dim3 gattn(S_LEN / 128, NH);               // 32 x 12
    attn_tc<<<gattn, 256, AT_SMEM>>>(qh, ql, kh, kl, vh, vl, ah, al);

    dim3 gout(DMODEL / 128, S_LEN / 128);      // 6 x 32
    out_proj<<<gout, 256, PROJ_SMEM>>>(ah, al, wh + WN, wl + WN, bo, out);
}

// round 12
// speedup vs baseline: 1.4856x; 1.1506x over previous
#include <cuda_runtime.h>
#include <cuda_fp16.h>
#include <math.h>
#include <stdint.h>

#define S_LEN 4096
#define DMODEL 768
#define NH 12
#define DK 64
#define XN (S_LEN * DMODEL)
#define WN (DMODEL * DMODEL)

__device__ __half g_xh[3 * XN], g_xl[3 * XN];
__device__ __half g_wh[2 * WN], g_wl[2 * WN];
__device__ __half g_qh[XN], g_ql[XN], g_kh[XN], g_vh[XN], g_vl[XN];
__device__ __half g_ah[XN];

__device__ __forceinline__ uint32_t smem_u32(const void* p) {
    uint32_t a;
    asm("{ .reg .u64 t; cvta.to.shared.u64 t, %1; cvt.u32.u64 %0, t; }" : "=r"(a) : "l"(p));
    return a;
}
__device__ __forceinline__ float ex2f(float x) {
    float r; asm("ex2.approx.ftz.f32 %0, %1;" : "=f"(r) : "f"(x)); return r;
}
__device__ __forceinline__ uint32_t pack_f16(float a, float b) {  // low=a, high=b
    __half2 h = __floats2half2_rn(a, b);
    return *(uint32_t*)&h;
}
__device__ __forceinline__ void ldsm4(uint32_t* r, uint32_t a) {
    asm volatile("ldmatrix.sync.aligned.m8n8.x4.shared.b16 {%0,%1,%2,%3}, [%4];"
                 : "=r"(r[0]), "=r"(r[1]), "=r"(r[2]), "=r"(r[3]) : "r"(a));
}
__device__ __forceinline__ void ldsm4t(uint32_t* r, uint32_t a) {
    asm volatile("ldmatrix.sync.aligned.m8n8.x4.trans.shared.b16 {%0,%1,%2,%3}, [%4];"
                 : "=r"(r[0]), "=r"(r[1]), "=r"(r[2]), "=r"(r[3]) : "r"(a));
}
__device__ __forceinline__ void mma16816(float* d, const uint32_t* a, const uint32_t* b) {
    asm volatile("mma.sync.aligned.m16n8k16.row.col.f32.f16.f16.f32 "
                 "{%0,%1,%2,%3}, {%4,%5,%6,%7}, {%8,%9}, {%0,%1,%2,%3};"
                 : "+f"(d[0]), "+f"(d[1]), "+f"(d[2]), "+f"(d[3])
                 : "r"(a[0]), "r"(a[1]), "r"(a[2]), "r"(a[3]), "r"(b[0]), "r"(b[1]));
}
__device__ __forceinline__ void cp16(uint32_t d, const void* s) {
    asm volatile("cp.async.cg.shared.global [%0], [%1], 16;" :: "r"(d), "l"(s));
}
#define CP_COMMIT() asm volatile("cp.async.commit_group;" ::: "memory")
#define CP_WAIT0()  asm volatile("cp.async.wait_group 0;" ::: "memory")
#define CP_WAIT1()  asm volatile("cp.async.wait_group 1;" ::: "memory")

__global__ void conv_hilo3(const float* __restrict__ a, const float* __restrict__ b,
                           const float* __restrict__ c,
                           __half* __restrict__ hi, __half* __restrict__ lo, int n4)
{
    int i = blockIdx.x * blockDim.x + threadIdx.x;
    if (i >= n4) return;
    const float* in = (blockIdx.z == 0) ? a : (blockIdx.z == 1) ? b : c;
    size_t off = (size_t)blockIdx.z * n4 + i;
    float4 v = ((const float4*)in)[i];
    __half2 h01 = __floats2half2_rn(v.x, v.y), h23 = __floats2half2_rn(v.z, v.w);
    ((__half2*)hi)[2 * off] = h01; ((__half2*)hi)[2 * off + 1] = h23;
    ((__half2*)lo)[2 * off]     = __floats2half2_rn(v.x - __half2float(h01.x), v.y - __half2float(h01.y));
    ((__half2*)lo)[2 * off + 1] = __floats2half2_rn(v.z - __half2float(h23.x), v.w - __half2float(h23.y));
}
__global__ void conv_hilo2(const float* __restrict__ a, const float* __restrict__ b,
                           __half* __restrict__ hi, __half* __restrict__ lo, int n4)
{
    int i = blockIdx.x * blockDim.x + threadIdx.x;
    if (i >= n4) return;
    const float* in = (blockIdx.z == 0) ? a : b;
    size_t off = (size_t)blockIdx.z * n4 + i;
    float4 v = ((const float4*)in)[i];
    __half2 h01 = __floats2half2_rn(v.x, v.y), h23 = __floats2half2_rn(v.z, v.w);
    ((__half2*)hi)[2 * off] = h01; ((__half2*)hi)[2 * off + 1] = h23;
    ((__half2*)lo)[2 * off]     = __floats2half2_rn(v.x - __half2float(h01.x), v.y - __half2float(h01.y));
    ((__half2*)lo)[2 * off + 1] = __floats2half2_rn(v.z - __half2float(h23.x), v.w - __half2float(h23.y));
}

// ---------------------------------------------------------------------------
// Projection GEMM core: 2-pass, 3 matrices per stage, cp.async 2-stage.
// BSPLIT=false: [A1=Xh | A2=Xl | B=Wh], Y = (Xh+Xl)·Wh
// BSPLIT=true : [A=Ah | B1=Wh | B2=Wl], Y = Ah·(Wh+Wl)
// ---------------------------------------------------------------------------
#define PM 5120
#define PSTG (3 * PM)
#define PROJ_SMEM (2 * PSTG * 2)

template <bool BSPLIT>
__device__ __forceinline__ void proj_stage_load(
    __half* st, const __half* M1, const __half* M2, const __half* M3,
    int m0, int n0, int k0, int tid)
{
    #pragma unroll
    for (int i = 0; i < 2; i++) {
        int idx = tid + i * 256;
        int r = idx >> 2, c8 = (idx & 3) * 8;
        size_t ms = (size_t)(m0 + r) * DMODEL + k0 + c8;
        size_t ns = (size_t)(n0 + r) * DMODEL + k0 + c8;
        uint32_t base = smem_u32(st + r * 40 + c8);
        if (BSPLIT) {
            cp16(base,              M1 + ms);   // Ah
            cp16(base + PM * 2,     M2 + ns);   // Wh
            cp16(base + 2 * PM * 2, M3 + ns);   // Wl
        } else {
            cp16(base,              M1 + ms);   // Xh
            cp16(base + PM * 2,     M2 + ms);   // Xl
            cp16(base + 2 * PM * 2, M3 + ns);   // Wh
        }
    }
    CP_COMMIT();
}

template <bool BSPLIT>
__device__ __forceinline__ void proj_gemm(
    float acc[2][8][4], __half* sm,
    const __half* M1, const __half* M2, const __half* M3,
    int m0, int n0, int tid, int wm, int wn, int lid)
{
    proj_stage_load<BSPLIT>(sm, M1, M2, M3, m0, n0, 0, tid);
    for (int t = 0; t < DMODEL / 32; t++) {
        CP_WAIT0();
        __syncthreads();
        if (t + 1 < DMODEL / 32)
            proj_stage_load<BSPLIT>(sm + ((t + 1) & 1) * PSTG, M1, M2, M3, m0, n0, (t + 1) * 32, tid);
        __half* P0 = sm + (t & 1) * PSTG;
        __half* P1 = P0 + PM;
        __half* P2 = P0 + 2 * PM;
        #pragma unroll
        for (int ks = 0; ks < 32; ks += 16) {
            const int ac = ks + ((lid >> 4) << 3);
            uint32_t a1[2][4], a2[2][4], b1[8][2], b2[8][2], r4[4];
            __half* Bh = BSPLIT ? P1 : P2;
            #pragma unroll
            for (int jp = 0; jp < 4; jp++) {
                int rB = 64 * wn + 16 * jp + (lid & 15);
                ldsm4(r4, smem_u32(Bh + rB * 40 + ac));
                b1[2*jp][0]=r4[0]; b1[2*jp][1]=r4[2]; b1[2*jp+1][0]=r4[1]; b1[2*jp+1][1]=r4[3];
                if (BSPLIT) {
                    ldsm4(r4, smem_u32(P2 + rB * 40 + ac));
                    b2[2*jp][0]=r4[0]; b2[2*jp][1]=r4[2]; b2[2*jp+1][0]=r4[1]; b2[2*jp+1][1]=r4[3];
                }
            }
            #pragma unroll
            for (int i = 0; i < 2; i++) {
                int rA = 32 * wm + 16 * i + (lid & 15);
                ldsm4(a1[i], smem_u32(P0 + rA * 40 + ac));
                if (!BSPLIT) ldsm4(a2[i], smem_u32(P1 + rA * 40 + ac));
            }
            #pragma unroll
            for (int i = 0; i < 2; i++) {
                #pragma unroll
                for (int j = 0; j < 8; j++) mma16816(acc[i][j], a1[i], b1[j]);
                #pragma unroll
                for (int j = 0; j < 8; j++)
                    mma16816(acc[i][j], BSPLIT ? a1[i] : a2[i], BSPLIT ? b2[j] : b1[j]);
            }
        }
        __syncthreads();
    }
}

__global__ void __launch_bounds__(256, 2) qkv_proj(
    const __half* __restrict__ xh, const __half* __restrict__ xl,
    const __half* __restrict__ Wh, const float* __restrict__ bias,
    __half* __restrict__ Qh, __half* __restrict__ Ql,
    __half* __restrict__ Kh, __half* __restrict__ Vh, __half* __restrict__ Vl)
{
    extern __shared__ __half sm[];
    const int tid = threadIdx.x, w = tid >> 5, lid = tid & 31;
    const int wm = w >> 1, wn = w & 1;
    const int m0 = blockIdx.y * 128, n0 = blockIdx.x * 128, z = blockIdx.z;
    const __half* Xh = xh + (size_t)z * XN;
    const __half* Xl = xl + (size_t)z * XN;
    __half* Yh = (z == 0) ? Qh : (z == 1) ? Kh : Vh;
    __half* Yl = (z == 0) ? Ql : (z == 1) ? nullptr : Vl;
    const float sc = (z == 0) ? 0.18033688011112042f : 1.0f;  // 0.125*log2(e)

    float acc[2][8][4] = {};
    proj_gemm<false>(acc, sm, Xh, Xl, Wh, m0, n0, tid, wm, wn, lid);

    #pragma unroll
    for (int i = 0; i < 2; i++) {
        int r = m0 + 32 * wm + 16 * i + (lid >> 2);
        #pragma unroll
        for (int j = 0; j < 8; j++) {
            int ng = n0 + 64 * wn + 8 * j + (lid & 3) * 2;
            float b0 = bias[ng], b1 = bias[ng + 1];
            int head = ng >> 6;
            #pragma unroll
            for (int hrow = 0; hrow < 2; hrow++) {
                int rr = r + hrow * 8;
                float f0 = (acc[i][j][2*hrow]   + b0) * sc;
                float f1 = (acc[i][j][2*hrow+1] + b1) * sc;
                uint32_t hp = pack_f16(f0, f1);
                size_t dst = ((size_t)head * S_LEN + rr) * DK + (ng & 63);
                *(uint32_t*)(Yh + dst) = hp;
                if (Yl) {
                    __half2 u = *(__half2*)&hp;
                    *(uint32_t*)(Yl + dst) = pack_f16(f0 - __half2float(u.x),
                                                      f1 - __half2float(u.y));
                }
            }
        }
    }
}

__global__ void __launch_bounds__(256, 2) out_proj(
    const __half* __restrict__ Ah,
    const __half* __restrict__ Wh, const __half* __restrict__ Wl,
    const float* __restrict__ bias, float* __restrict__ Yf)
{
    extern __shared__ __half sm[];
    const int tid = threadIdx.x, w = tid >> 5, lid = tid & 31;
    const int wm = w >> 1, wn = w & 1;
    const int m0 = blockIdx.y * 128, n0 = blockIdx.x * 128;

    float acc[2][8][4] = {};
    proj_gemm<true>(acc, sm, Ah, Wh, Wl, m0, n0, tid, wm, wn, lid);

    #pragma unroll
    for (int i = 0; i < 2; i++) {
        int r = m0 + 32 * wm + 16 * i + (lid >> 2);
        #pragma unroll
        for (int j = 0; j < 8; j++) {
            int ng = n0 + 64 * wn + 8 * j + (lid & 3) * 2;
            float b0 = bias[ng], b1 = bias[ng + 1];
            #pragma unroll
            for (int hrow = 0; hrow < 2; hrow++) {
                int rr = r + hrow * 8;
                Yf[(size_t)rr * DMODEL + ng]     = acc[i][j][2*hrow]   + b0;
                Yf[(size_t)rr * DMODEL + ng + 1] = acc[i][j][2*hrow+1] + b1;
            }
        }
    }
}

// ---------------------------------------------------------------------------
// Flash attention: CTA=(head, 128 q rows), 8 warps, Bc=64, fp16 2-pass.
// 3-stage cp.async pipeline; stage 2 overlays the (dead-after-hoist) Q region.
// smem 90KB + 128 regs -> 2 CTAs/SM for cross-CTA phase interleaving.
// Layout (rows of [QS]): [Qh 128 | Ql 128 | S0 192 | S1 192]; S2 = row 0.
// ---------------------------------------------------------------------------
#define QS 72
#define NT (S_LEN / 64)
#define AT_SMEM (640 * QS * 2)   // 92160 B

__device__ __forceinline__ void attn_stage_load(
    __half (*SN)[QS], const __half* Kh, const __half* Vh, const __half* Vl,
    size_t hbase, int kv0, int tid)
{
    #pragma unroll
    for (int i = 0; i < 2; i++) {
        int idx = tid + i * 256;
        int r = idx >> 3, c8 = (idx & 7) * 8;
        size_t src = hbase + (size_t)(kv0 + r) * DK + c8;
        cp16(smem_u32(&SN[r][c8]),       Kh + src);
        cp16(smem_u32(&SN[64 + r][c8]),  Vh + src);
        cp16(smem_u32(&SN[128 + r][c8]), Vl + src);
    }
    CP_COMMIT();
}

__global__ void __launch_bounds__(256, 2) attn_tc(
    const __half* __restrict__ Qh, const __half* __restrict__ Ql,
    const __half* __restrict__ Kh,
    const __half* __restrict__ Vh, const __half* __restrict__ Vl,
    __half* __restrict__ Ah)
{
    extern __shared__ __half sm[];
    __half (*ROWS)[QS] = (__half(*)[QS])sm;
    __half (*Qhs)[QS] = ROWS;           // rows 0..127
    __half (*Qls)[QS] = ROWS + 128;     // rows 128..255
    __half (*stg[3])[QS] = { ROWS + 256, ROWS + 448, ROWS };  // S2 overlays Q

    const int tid = threadIdx.x, w = tid >> 5, lid = tid & 31;
    const int h = blockIdx.y, q0 = blockIdx.x * 128;
    const size_t hbase = (size_t)h * S_LEN * DK;

    #pragma unroll
    for (int i = 0; i < 4; i++) {
        int idx = tid + i * 256;
        int r = idx >> 3, c8 = (idx & 7) * 8;
        size_t src = hbase + (size_t)(q0 + r) * DK + c8;
        *(uint4*)&Qhs[r][c8] = *(const uint4*)(Qh + src);
        *(uint4*)&Qls[r][c8] = *(const uint4*)(Ql + src);
    }
    attn_stage_load(stg[0], Kh, Vh, Vl, hbase, 0,  tid);
    attn_stage_load(stg[1], Kh, Vh, Vl, hbase, 64, tid);
    __syncthreads();                    // Q visible to all warps

    uint32_t qhf[4][4], qlf[4][4];
    #pragma unroll
    for (int ks = 0; ks < 4; ks++) {
        const int ac = 16 * ks + ((lid >> 4) << 3);
        ldsm4(qhf[ks], smem_u32(&Qhs[16 * w + (lid & 15)][ac]));
        ldsm4(qlf[ks], smem_u32(&Qls[16 * w + (lid & 15)][ac]));
    }

    float O[8][4] = {};
    float m0r = -INFINITY, m1r = -INFINITY, l0r = 0.f, l1r = 0.f;

    for (int t = 0; t < NT; t++) {
        if (t == NT - 1) { CP_WAIT0(); } else { CP_WAIT1(); }
        __syncthreads();                // also orders Q-hoist before S2 overwrite (t=0)
        if (t + 2 < NT)
            attn_stage_load(stg[(t + 2) % 3], Kh, Vh, Vl, hbase, (t + 2) * 64, tid);

        __half (*Khs)[QS] = stg[t % 3];
        __half (*Vhs)[QS] = Khs + 64;
        __half (*Vls)[QS] = Khs + 128;

        // S = (Qh + Ql) . Kh^T  -- 2 passes
        float s[8][4] = {};
        #pragma unroll
        for (int ks = 0; ks < 4; ks++) {
            const int ac = 16 * ks + ((lid >> 4) << 3);
            uint32_t bh[8][2], r4[4];
            #pragma unroll
            for (int jp = 0; jp < 4; jp++) {
                int rB = 16 * jp + (lid & 15);
                ldsm4(r4, smem_u32(&Khs[rB][ac]));
                bh[2*jp][0]=r4[0]; bh[2*jp][1]=r4[2]; bh[2*jp+1][0]=r4[1]; bh[2*jp+1][1]=r4[3];
            }
            #pragma unroll
            for (int j = 0; j < 8; j++) mma16816(s[j], qhf[ks], bh[j]);
            #pragma unroll
            for (int j = 0; j < 8; j++) mma16816(s[j], qlf[ks], bh[j]);
        }

        // online softmax (log2 domain; scale folded into Q)
        float rm0 = -INFINITY, rm1 = -INFINITY;
        #pragma unroll
        for (int j = 0; j < 8; j++) {
            rm0 = fmaxf(rm0, fmaxf(s[j][0], s[j][1]));
            rm1 = fmaxf(rm1, fmaxf(s[j][2], s[j][3]));
        }
        rm0 = fmaxf(rm0, __shfl_xor_sync(~0u, rm0, 1)); rm0 = fmaxf(rm0, __shfl_xor_sync(~0u, rm0, 2));
        rm1 = fmaxf(rm1, __shfl_xor_sync(~0u, rm1, 1)); rm1 = fmaxf(rm1, __shfl_xor_sync(~0u, rm1, 2));
        float mn0 = fmaxf(m0r, rm0), mn1 = fmaxf(m1r, rm1);
        float c0 = ex2f(m0r - mn0), c1 = ex2f(m1r - mn1);
        m0r = mn0; m1r = mn1;
        float s0 = 0.f, s1 = 0.f;
        #pragma unroll
        for (int j = 0; j < 8; j++) {
            s[j][0] = ex2f(s[j][0] - mn0); s[j][1] = ex2f(s[j][1] - mn0);
            s[j][2] = ex2f(s[j][2] - mn1); s[j][3] = ex2f(s[j][3] - mn1);
            s0 += s[j][0] + s[j][1]; s1 += s[j][2] + s[j][3];
        }
        s0 += __shfl_xor_sync(~0u, s0, 1); s0 += __shfl_xor_sync(~0u, s0, 2);
        s1 += __shfl_xor_sync(~0u, s1, 1); s1 += __shfl_xor_sync(~0u, s1, 2);
        l0r = l0r * c0 + s0; l1r = l1r * c1 + s1;
        #pragma unroll
        for (int j = 0; j < 8; j++) { O[j][0] *= c0; O[j][1] *= c0; O[j][2] *= c1; O[j][3] *= c1; }

        // P -> fp16 A-fragments (hi only)
        uint32_t ph[4][4];
        #pragma unroll
        for (int j2 = 0; j2 < 4; j2++) {
            int t0 = 2 * j2, t1 = t0 + 1;
            ph[j2][0] = pack_f16(s[t0][0], s[t0][1]); ph[j2][1] = pack_f16(s[t0][2], s[t0][3]);
            ph[j2][2] = pack_f16(s[t1][0], s[t1][1]); ph[j2][3] = pack_f16(s[t1][2], s[t1][3]);
        }

        // O += Ph . (Vh + Vl)  -- 2 passes
        #pragma unroll
        for (int j2 = 0; j2 < 4; j2++) {
            uint32_t vh[8][2], vl[8][2], r4[4];
            #pragma unroll
            for (int np = 0; np < 4; np++) {
                int rV = 16 * j2 + (lid & 15), cV = 16 * np + ((lid >> 4) << 3);
                ldsm4t(r4, smem_u32(&Vhs[rV][cV]));
                vh[2*np][0]=r4[0]; vh[2*np][1]=r4[1]; vh[2*np+1][0]=r4[2]; vh[2*np+1][1]=r4[3];
                ldsm4t(r4, smem_u32(&Vls[rV][cV]));
                vl[2*np][0]=r4[0]; vl[2*np][1]=r4[1]; vl[2*np+1][0]=r4[2]; vl[2*np+1][1]=r4[3];
            }
            #pragma unroll
            for (int tt = 0; tt < 8; tt++) mma16816(O[tt], ph[j2], vh[tt]);
            #pragma unroll
            for (int tt = 0; tt < 8; tt++) mma16816(O[tt], ph[j2], vl[tt]);
        }
    }

    float i0 = 1.f / l0r, i1 = 1.f / l1r;
    #pragma unroll
    for (int t = 0; t < 8; t++) {
        int c = h * DK + 8 * t + (lid & 3) * 2;
        int r0 = q0 + 16 * w + (lid >> 2);
        #pragma unroll
        for (int hrow = 0; hrow < 2; hrow++) {
            float f0 = O[t][2*hrow]   * (hrow ? i1 : i0);
            float f1 = O[t][2*hrow+1] * (hrow ? i1 : i0);
            size_t dst = (size_t)(r0 + hrow * 8) * DMODEL + c;
            *(uint32_t*)(Ah + dst) = pack_f16(f0, f1);
        }
    }
}

extern "C" void kernel_launch(void* const* d_in, const int* in_sizes, int n_in,
                              void* d_out, int out_size)
{
    const float* q  = (const float*)d_in[0];
    const float* k  = (const float*)d_in[1];
    const float* v  = (const float*)d_in[2];
    const float* Wq = (const float*)d_in[3];
    const float* bq = (const float*)d_in[4];
    const float* Wo = (const float*)d_in[5];
    const float* bo = (const float*)d_in[6];
    float* out = (float*)d_out;

    __half *xh, *xl, *wh, *wl, *qh, *ql, *kh, *vh, *vl, *ah;
    cudaGetSymbolAddress((void**)&xh, g_xh); cudaGetSymbolAddress((void**)&xl, g_xl);
    cudaGetSymbolAddress((void**)&wh, g_wh); cudaGetSymbolAddress((void**)&wl, g_wl);
    cudaGetSymbolAddress((void**)&qh, g_qh); cudaGetSymbolAddress((void**)&ql, g_ql);
    cudaGetSymbolAddress((void**)&kh, g_kh);
    cudaGetSymbolAddress((void**)&vh, g_vh); cudaGetSymbolAddress((void**)&vl, g_vl);
    cudaGetSymbolAddress((void**)&ah, g_ah);

    cudaFuncSetAttribute(attn_tc,  cudaFuncAttributeMaxDynamicSharedMemorySize, AT_SMEM);
    cudaFuncSetAttribute(qkv_proj, cudaFuncAttributeMaxDynamicSharedMemorySize, PROJ_SMEM);
    cudaFuncSetAttribute(out_proj, cudaFuncAttributeMaxDynamicSharedMemorySize, PROJ_SMEM);

    dim3 gc3(XN / 4 / 256, 1, 3);
    conv_hilo3<<<gc3, 256>>>(q, k, v, xh, xl, XN / 4);
    dim3 gc2(WN / 4 / 256, 1, 2);
    conv_hilo2<<<gc2, 256>>>(Wq, Wo, wh, wl, WN / 4);

    dim3 gqkv(DMODEL / 128, S_LEN / 128, 3);   // 6 x 32 x 3
    qkv_proj<<<gqkv, 256, PROJ_SMEM>>>(xh, xl, wh, bq, qh, ql, kh, vh, vl);

    dim3 gattn(S_LEN / 128, NH);               // 32 x 12
    attn_tc<<<gattn, 256, AT_SMEM>>>(qh, ql, kh, vh, vl, ah);

    dim3 gout(DMODEL / 128, S_LEN / 128);      // 6 x 32
    out_proj<<<gout, 256, PROJ_SMEM>>>(ah, wh + WN, wl + WN, bo, out);
}

// round 13
// speedup vs baseline: 1.7431x; 1.1733x over previous
#include <cuda_runtime.h>
#include <cuda_fp16.h>
#include <math.h>
#include <stdint.h>

#define S_LEN 4096
#define DMODEL 768
#define NH 12
#define DK 64
#define XN (S_LEN * DMODEL)
#define WN (DMODEL * DMODEL)

__device__ __half g_xh[3 * XN], g_xl[3 * XN];
__device__ __half g_wh[2 * WN], g_wl[2 * WN];
__device__ __half g_qh[XN], g_ql[XN], g_kh[XN], g_vh[XN];
__device__ __half g_ah[XN];

__device__ __forceinline__ uint32_t smem_u32(const void* p) {
    uint32_t a;
    asm("{ .reg .u64 t; cvta.to.shared.u64 t, %1; cvt.u32.u64 %0, t; }" : "=r"(a) : "l"(p));
    return a;
}
__device__ __forceinline__ float ex2f(float x) {
    float r; asm("ex2.approx.ftz.f32 %0, %1;" : "=f"(r) : "f"(x)); return r;
}
__device__ __forceinline__ uint32_t pack_f16(float a, float b) {  // low=a, high=b
    __half2 h = __floats2half2_rn(a, b);
    return *(uint32_t*)&h;
}
__device__ __forceinline__ void ldsm4(uint32_t* r, uint32_t a) {
    asm volatile("ldmatrix.sync.aligned.m8n8.x4.shared.b16 {%0,%1,%2,%3}, [%4];"
                 : "=r"(r[0]), "=r"(r[1]), "=r"(r[2]), "=r"(r[3]) : "r"(a));
}
__device__ __forceinline__ void ldsm4t(uint32_t* r, uint32_t a) {
    asm volatile("ldmatrix.sync.aligned.m8n8.x4.trans.shared.b16 {%0,%1,%2,%3}, [%4];"
                 : "=r"(r[0]), "=r"(r[1]), "=r"(r[2]), "=r"(r[3]) : "r"(a));
}
__device__ __forceinline__ void mma16816(float* d, const uint32_t* a, const uint32_t* b) {
    asm volatile("mma.sync.aligned.m16n8k16.row.col.f32.f16.f16.f32 "
                 "{%0,%1,%2,%3}, {%4,%5,%6,%7}, {%8,%9}, {%0,%1,%2,%3};"
                 : "+f"(d[0]), "+f"(d[1]), "+f"(d[2]), "+f"(d[3])
                 : "r"(a[0]), "r"(a[1]), "r"(a[2]), "r"(a[3]), "r"(b[0]), "r"(b[1]));
}
__device__ __forceinline__ void cp16(uint32_t d, const void* s) {
    asm volatile("cp.async.cg.shared.global [%0], [%1], 16;" :: "r"(d), "l"(s));
}
#define CP_COMMIT() asm volatile("cp.async.commit_group;" ::: "memory")
#define CP_WAIT0()  asm volatile("cp.async.wait_group 0;" ::: "memory")
#define CP_WAIT1()  asm volatile("cp.async.wait_group 1;" ::: "memory")

__global__ void conv_hilo3(const float* __restrict__ a, const float* __restrict__ b,
                           const float* __restrict__ c,
                           __half* __restrict__ hi, __half* __restrict__ lo, int n4)
{
    int i = blockIdx.x * blockDim.x + threadIdx.x;
    if (i >= n4) return;
    const float* in = (blockIdx.z == 0) ? a : (blockIdx.z == 1) ? b : c;
    size_t off = (size_t)blockIdx.z * n4 + i;
    float4 v = ((const float4*)in)[i];
    __half2 h01 = __floats2half2_rn(v.x, v.y), h23 = __floats2half2_rn(v.z, v.w);
    ((__half2*)hi)[2 * off] = h01; ((__half2*)hi)[2 * off + 1] = h23;
    ((__half2*)lo)[2 * off]     = __floats2half2_rn(v.x - __half2float(h01.x), v.y - __half2float(h01.y));
    ((__half2*)lo)[2 * off + 1] = __floats2half2_rn(v.z - __half2float(h23.x), v.w - __half2float(h23.y));
}
__global__ void conv_hilo2(const float* __restrict__ a, const float* __restrict__ b,
                           __half* __restrict__ hi, __half* __restrict__ lo, int n4)
{
    int i = blockIdx.x * blockDim.x + threadIdx.x;
    if (i >= n4) return;
    const float* in = (blockIdx.z == 0) ? a : b;
    size_t off = (size_t)blockIdx.z * n4 + i;
    float4 v = ((const float4*)in)[i];
    __half2 h01 = __floats2half2_rn(v.x, v.y), h23 = __floats2half2_rn(v.z, v.w);
    ((__half2*)hi)[2 * off] = h01; ((__half2*)hi)[2 * off + 1] = h23;
    ((__half2*)lo)[2 * off]     = __floats2half2_rn(v.x - __half2float(h01.x), v.y - __half2float(h01.y));
    ((__half2*)lo)[2 * off + 1] = __floats2half2_rn(v.z - __half2float(h23.x), v.w - __half2float(h23.y));
}

// ---------------------------------------------------------------------------
// Projection GEMM core: 2-pass, 3 matrices per stage, cp.async 2-stage.
// BSPLIT=false: [A1=Xh | A2=Xl | B=Wh], Y = (Xh+Xl)·Wh
// BSPLIT=true : [A=Ah | B1=Wh | B2=Wl], Y = Ah·(Wh+Wl)
// ---------------------------------------------------------------------------
#define PM 5120
#define PSTG (3 * PM)
#define PROJ_SMEM (2 * PSTG * 2)

template <bool BSPLIT>
__device__ __forceinline__ void proj_stage_load(
    __half* st, const __half* M1, const __half* M2, const __half* M3,
    int m0, int n0, int k0, int tid)
{
    #pragma unroll
    for (int i = 0; i < 2; i++) {
        int idx = tid + i * 256;
        int r = idx >> 2, c8 = (idx & 3) * 8;
        size_t ms = (size_t)(m0 + r) * DMODEL + k0 + c8;
        size_t ns = (size_t)(n0 + r) * DMODEL + k0 + c8;
        uint32_t base = smem_u32(st + r * 40 + c8);
        if (BSPLIT) {
            cp16(base,              M1 + ms);   // Ah
            cp16(base + PM * 2,     M2 + ns);   // Wh
            cp16(base + 2 * PM * 2, M3 + ns);   // Wl
        } else {
            cp16(base,              M1 + ms);   // Xh
            cp16(base + PM * 2,     M2 + ms);   // Xl
            cp16(base + 2 * PM * 2, M3 + ns);   // Wh
        }
    }
    CP_COMMIT();
}

template <bool BSPLIT>
__device__ __forceinline__ void proj_gemm(
    float acc[2][8][4], __half* sm,
    const __half* M1, const __half* M2, const __half* M3,
    int m0, int n0, int tid, int wm, int wn, int lid)
{
    proj_stage_load<BSPLIT>(sm, M1, M2, M3, m0, n0, 0, tid);
    for (int t = 0; t < DMODEL / 32; t++) {
        CP_WAIT0();
        __syncthreads();
        if (t + 1 < DMODEL / 32)
            proj_stage_load<BSPLIT>(sm + ((t + 1) & 1) * PSTG, M1, M2, M3, m0, n0, (t + 1) * 32, tid);
        __half* P0 = sm + (t & 1) * PSTG;
        __half* P1 = P0 + PM;
        __half* P2 = P0 + 2 * PM;
        #pragma unroll
        for (int ks = 0; ks < 32; ks += 16) {
            const int ac = ks + ((lid >> 4) << 3);
            uint32_t a1[2][4], a2[2][4], b1[8][2], b2[8][2], r4[4];
            __half* Bh = BSPLIT ? P1 : P2;
            #pragma unroll
            for (int jp = 0; jp < 4; jp++) {
                int rB = 64 * wn + 16 * jp + (lid & 15);
                ldsm4(r4, smem_u32(Bh + rB * 40 + ac));
                b1[2*jp][0]=r4[0]; b1[2*jp][1]=r4[2]; b1[2*jp+1][0]=r4[1]; b1[2*jp+1][1]=r4[3];
                if (BSPLIT) {
                    ldsm4(r4, smem_u32(P2 + rB * 40 + ac));
                    b2[2*jp][0]=r4[0]; b2[2*jp][1]=r4[2]; b2[2*jp+1][0]=r4[1]; b2[2*jp+1][1]=r4[3];
                }
            }
            #pragma unroll
            for (int i = 0; i < 2; i++) {
                int rA = 32 * wm + 16 * i + (lid & 15);
                ldsm4(a1[i], smem_u32(P0 + rA * 40 + ac));
                if (!BSPLIT) ldsm4(a2[i], smem_u32(P1 + rA * 40 + ac));
            }
            #pragma unroll
            for (int i = 0; i < 2; i++) {
                #pragma unroll
                for (int j = 0; j < 8; j++) mma16816(acc[i][j], a1[i], b1[j]);
                #pragma unroll
                for (int j = 0; j < 8; j++)
                    mma16816(acc[i][j], BSPLIT ? a1[i] : a2[i], BSPLIT ? b2[j] : b1[j]);
            }
        }
        __syncthreads();
    }
}

__global__ void __launch_bounds__(256, 2) qkv_proj(
    const __half* __restrict__ xh, const __half* __restrict__ xl,
    const __half* __restrict__ Wh, const float* __restrict__ bias,
    __half* __restrict__ Qh, __half* __restrict__ Ql,
    __half* __restrict__ Kh, __half* __restrict__ Vh)
{
    extern __shared__ __half sm[];
    const int tid = threadIdx.x, w = tid >> 5, lid = tid & 31;
    const int wm = w >> 1, wn = w & 1;
    const int m0 = blockIdx.y * 128, n0 = blockIdx.x * 128, z = blockIdx.z;
    const __half* Xh = xh + (size_t)z * XN;
    const __half* Xl = xl + (size_t)z * XN;
    __half* Yh = (z == 0) ? Qh : (z == 1) ? Kh : Vh;
    __half* Yl = (z == 0) ? Ql : nullptr;
    const float sc = (z == 0) ? 0.18033688011112042f : 1.0f;  // 0.125*log2(e)

    float acc[2][8][4] = {};
    proj_gemm<false>(acc, sm, Xh, Xl, Wh, m0, n0, tid, wm, wn, lid);

    #pragma unroll
    for (int i = 0; i < 2; i++) {
        int r = m0 + 32 * wm + 16 * i + (lid >> 2);
        #pragma unroll
        for (int j = 0; j < 8; j++) {
            int ng = n0 + 64 * wn + 8 * j + (lid & 3) * 2;
            float b0 = bias[ng], b1 = bias[ng + 1];
            int head = ng >> 6;
            #pragma unroll
            for (int hrow = 0; hrow < 2; hrow++) {
                int rr = r + hrow * 8;
                float f0 = (acc[i][j][2*hrow]   + b0) * sc;
                float f1 = (acc[i][j][2*hrow+1] + b1) * sc;
                uint32_t hp = pack_f16(f0, f1);
                size_t dst = ((size_t)head * S_LEN + rr) * DK + (ng & 63);
                *(uint32_t*)(Yh + dst) = hp;
                if (Yl) {
                    __half2 u = *(__half2*)&hp;
                    *(uint32_t*)(Yl + dst) = pack_f16(f0 - __half2float(u.x),
                                                      f1 - __half2float(u.y));
                }
            }
        }
    }
}

__global__ void __launch_bounds__(256, 2) out_proj(
    const __half* __restrict__ Ah,
    const __half* __restrict__ Wh, const __half* __restrict__ Wl,
    const float* __restrict__ bias, float* __restrict__ Yf)
{
    extern __shared__ __half sm[];
    const int tid = threadIdx.x, w = tid >> 5, lid = tid & 31;
    const int wm = w >> 1, wn = w & 1;
    const int m0 = blockIdx.y * 128, n0 = blockIdx.x * 128;

    float acc[2][8][4] = {};
    proj_gemm<true>(acc, sm, Ah, Wh, Wl, m0, n0, tid, wm, wn, lid);

    #pragma unroll
    for (int i = 0; i < 2; i++) {
        int r = m0 + 32 * wm + 16 * i + (lid >> 2);
        #pragma unroll
        for (int j = 0; j < 8; j++) {
            int ng = n0 + 64 * wn + 8 * j + (lid & 3) * 2;
            float b0 = bias[ng], b1 = bias[ng + 1];
            #pragma unroll
            for (int hrow = 0; hrow < 2; hrow++) {
                int rr = r + hrow * 8;
                Yf[(size_t)rr * DMODEL + ng]     = acc[i][j][2*hrow]   + b0;
                Yf[(size_t)rr * DMODEL + ng + 1] = acc[i][j][2*hrow+1] + b1;
            }
        }
    }
}

// ---------------------------------------------------------------------------
// Flash attention: CTA=(head, 128 q rows), 8 warps, Bc=64.
// S = (Qh+Ql)·Kh (2 passes); O = Ph·Vh (1 pass, Vl dropped).
// 3-stage cp.async pipeline of [Kh 64 | Vh 64]; stage 2 overlays dead Qh rows.
// Layout rows: [Qh 0-127 | Ql 128-255 | S0 256-383 | S1 384-511]; S2 = rows 0-127.
// smem 73.7KB, 2 CTAs/SM (reg-capped).
// ---------------------------------------------------------------------------
#define QS 72
#define NT (S_LEN / 64)
#define AT_SMEM (512 * QS * 2)   // 73728 B

__device__ __forceinline__ void attn_stage_load(
    __half (*SN)[QS], const __half* Kh, const __half* Vh,
    size_t hbase, int kv0, int tid)
{
    #pragma unroll
    for (int i = 0; i < 2; i++) {
        int idx = tid + i * 256;
        int r = idx >> 3, c8 = (idx & 7) * 8;
        size_t src = hbase + (size_t)(kv0 + r) * DK + c8;
        cp16(smem_u32(&SN[r][c8]),      Kh + src);
        cp16(smem_u32(&SN[64 + r][c8]), Vh + src);
    }
    CP_COMMIT();
}

__global__ void __launch_bounds__(256, 2) attn_tc(
    const __half* __restrict__ Qh, const __half* __restrict__ Ql,
    const __half* __restrict__ Kh, const __half* __restrict__ Vh,
    __half* __restrict__ Ah)
{
    extern __shared__ __half sm[];
    __half (*ROWS)[QS] = (__half(*)[QS])sm;
    __half (*Qhs)[QS] = ROWS;           // rows 0..127
    __half (*Qls)[QS] = ROWS + 128;     // rows 128..255
    __half (*stg[3])[QS] = { ROWS + 256, ROWS + 384, ROWS };  // S2 overlays Qh

    const int tid = threadIdx.x, w = tid >> 5, lid = tid & 31;
    const int h = blockIdx.y, q0 = blockIdx.x * 128;
    const size_t hbase = (size_t)h * S_LEN * DK;

    #pragma unroll
    for (int i = 0; i < 4; i++) {
        int idx = tid + i * 256;
        int r = idx >> 3, c8 = (idx & 7) * 8;
        size_t src = hbase + (size_t)(q0 + r) * DK + c8;
        *(uint4*)&Qhs[r][c8] = *(const uint4*)(Qh + src);
        *(uint4*)&Qls[r][c8] = *(const uint4*)(Ql + src);
    }
    attn_stage_load(stg[0], Kh, Vh, hbase, 0,  tid);
    attn_stage_load(stg[1], Kh, Vh, hbase, 64, tid);
    __syncthreads();                    // Q visible to all warps

    uint32_t qhf[4][4], qlf[4][4];
    #pragma unroll
    for (int ks = 0; ks < 4; ks++) {
        const int ac = 16 * ks + ((lid >> 4) << 3);
        ldsm4(qhf[ks], smem_u32(&Qhs[16 * w + (lid & 15)][ac]));
        ldsm4(qlf[ks], smem_u32(&Qls[16 * w + (lid & 15)][ac]));
    }

    float O[8][4] = {};
    float m0r = -INFINITY, m1r = -INFINITY, l0r = 0.f, l1r = 0.f;

    for (int t = 0; t < NT; t++) {
        if (t == NT - 1) { CP_WAIT0(); } else { CP_WAIT1(); }
        __syncthreads();                // orders Q-hoist before S2 overwrite (t=0)
        if (t + 2 < NT)
            attn_stage_load(stg[(t + 2) % 3], Kh, Vh, hbase, (t + 2) * 64, tid);

        __half (*Khs)[QS] = stg[t % 3];
        __half (*Vhs)[QS] = Khs + 64;

        // S = (Qh + Ql) . Kh^T  -- 2 passes
        float s[8][4] = {};
        #pragma unroll
        for (int ks = 0; ks < 4; ks++) {
            const int ac = 16 * ks + ((lid >> 4) << 3);
            uint32_t bh[8][2], r4[4];
            #pragma unroll
            for (int jp = 0; jp < 4; jp++) {
                int rB = 16 * jp + (lid & 15);
                ldsm4(r4, smem_u32(&Khs[rB][ac]));
                bh[2*jp][0]=r4[0]; bh[2*jp][1]=r4[2]; bh[2*jp+1][0]=r4[1]; bh[2*jp+1][1]=r4[3];
            }
            #pragma unroll
            for (int j = 0; j < 8; j++) mma16816(s[j], qhf[ks], bh[j]);
            #pragma unroll
            for (int j = 0; j < 8; j++) mma16816(s[j], qlf[ks], bh[j]);
        }

        // online softmax (log2 domain; scale folded into Q)
        float rm0 = -INFINITY, rm1 = -INFINITY;
        #pragma unroll
        for (int j = 0; j < 8; j++) {
            rm0 = fmaxf(rm0, fmaxf(s[j][0], s[j][1]));
            rm1 = fmaxf(rm1, fmaxf(s[j][2], s[j][3]));
        }
        rm0 = fmaxf(rm0, __shfl_xor_sync(~0u, rm0, 1)); rm0 = fmaxf(rm0, __shfl_xor_sync(~0u, rm0, 2));
        rm1 = fmaxf(rm1, __shfl_xor_sync(~0u, rm1, 1)); rm1 = fmaxf(rm1, __shfl_xor_sync(~0u, rm1, 2));
        float mn0 = fmaxf(m0r, rm0), mn1 = fmaxf(m1r, rm1);
        float c0 = ex2f(m0r - mn0), c1 = ex2f(m1r - mn1);
        m0r = mn0; m1r = mn1;
        float s0 = 0.f, s1 = 0.f;
        #pragma unroll
        for (int j = 0; j < 8; j++) {
            s[j][0] = ex2f(s[j][0] - mn0); s[j][1] = ex2f(s[j][1] - mn0);
            s[j][2] = ex2f(s[j][2] - mn1); s[j][3] = ex2f(s[j][3] - mn1);
            s0 += s[j][0] + s[j][1]; s1 += s[j][2] + s[j][3];
        }
        s0 += __shfl_xor_sync(~0u, s0, 1); s0 += __shfl_xor_sync(~0u, s0, 2);
        s1 += __shfl_xor_sync(~0u, s1, 1); s1 += __shfl_xor_sync(~0u, s1, 2);
        l0r = l0r * c0 + s0; l1r = l1r * c1 + s1;
        #pragma unroll
        for (int j = 0; j < 8; j++) { O[j][0] *= c0; O[j][1] *= c0; O[j][2] *= c1; O[j][3] *= c1; }

        // P -> fp16 A-fragments (hi only)
        uint32_t ph[4][4];
        #pragma unroll
        for (int j2 = 0; j2 < 4; j2++) {
            int t0 = 2 * j2, t1 = t0 + 1;
            ph[j2][0] = pack_f16(s[t0][0], s[t0][1]); ph[j2][1] = pack_f16(s[t0][2], s[t0][3]);
            ph[j2][2] = pack_f16(s[t1][0], s[t1][1]); ph[j2][3] = pack_f16(s[t1][2], s[t1][3]);
        }

        // O += Ph . Vh  -- 1 pass
        #pragma unroll
        for (int j2 = 0; j2 < 4; j2++) {
            uint32_t vh[8][2], r4[4];
            #pragma unroll
            for (int np = 0; np < 4; np++) {
                int rV = 16 * j2 + (lid & 15), cV = 16 * np + ((lid >> 4) << 3);
                ldsm4t(r4, smem_u32(&Vhs[rV][cV]));
                vh[2*np][0]=r4[0]; vh[2*np][1]=r4[1]; vh[2*np+1][0]=r4[2]; vh[2*np+1][1]=r4[3];
            }
            #pragma unroll
            for (int tt = 0; tt < 8; tt++) mma16816(O[tt], ph[j2], vh[tt]);
        }
    }

    float i0 = 1.f / l0r, i1 = 1.f / l1r;
    #pragma unroll
    for (int t = 0; t < 8; t++) {
        int c = h * DK + 8 * t + (lid & 3) * 2;
        int r0 = q0 + 16 * w + (lid >> 2);
        #pragma unroll
        for (int hrow = 0; hrow < 2; hrow++) {
            float f0 = O[t][2*hrow]   * (hrow ? i1 : i0);
            float f1 = O[t][2*hrow+1] * (hrow ? i1 : i0);
            size_t dst = (size_t)(r0 + hrow * 8) * DMODEL + c;
            *(uint32_t*)(Ah + dst) = pack_f16(f0, f1);
        }
    }
}

extern "C" void kernel_launch(void* const* d_in, const int* in_sizes, int n_in,
                              void* d_out, int out_size)
{
    const float* q  = (const float*)d_in[0];
    const float* k  = (const float*)d_in[1];
    const float* v  = (const float*)d_in[2];
    const float* Wq = (const float*)d_in[3];
    const float* bq = (const float*)d_in[4];
    const float* Wo = (const float*)d_in[5];
    const float* bo = (const float*)d_in[6];
    float* out = (float*)d_out;

    __half *xh, *xl, *wh, *wl, *qh, *ql, *kh, *vh, *ah;
    cudaGetSymbolAddress((void**)&xh, g_xh); cudaGetSymbolAddress((void**)&xl, g_xl);
    cudaGetSymbolAddress((void**)&wh, g_wh); cudaGetSymbolAddress((void**)&wl, g_wl);
    cudaGetSymbolAddress((void**)&qh, g_qh); cudaGetSymbolAddress((void**)&ql, g_ql);
    cudaGetSymbolAddress((void**)&kh, g_kh); cudaGetSymbolAddress((void**)&vh, g_vh);
    cudaGetSymbolAddress((void**)&ah, g_ah);

    cudaFuncSetAttribute(attn_tc,  cudaFuncAttributeMaxDynamicSharedMemorySize, AT_SMEM);
    cudaFuncSetAttribute(qkv_proj, cudaFuncAttributeMaxDynamicSharedMemorySize, PROJ_SMEM);
    cudaFuncSetAttribute(out_proj, cudaFuncAttributeMaxDynamicSharedMemorySize, PROJ_SMEM);

    dim3 gc3(XN / 4 / 256, 1, 3);
    conv_hilo3<<<gc3, 256>>>(q, k, v, xh, xl, XN / 4);
    dim3 gc2(WN / 4 / 256, 1, 2);
    conv_hilo2<<<gc2, 256>>>(Wq, Wo, wh, wl, WN / 4);

    dim3 gqkv(DMODEL / 128, S_LEN / 128, 3);   // 6 x 32 x 3
    qkv_proj<<<gqkv, 256, PROJ_SMEM>>>(xh, xl, wh, bq, qh, ql, kh, vh);

    dim3 gattn(S_LEN / 128, NH);               // 32 x 12
    attn_tc<<<gattn, 256, AT_SMEM>>>(qh, ql, kh, vh, ah);

    dim3 gout(DMODEL / 128, S_LEN / 128);      // 6 x 32
    out_proj<<<gout, 256, PROJ_SMEM>>>(ah, wh + WN, wl + WN, bo, out);
}

// round 14
// speedup vs baseline: 2.2700x; 1.3023x over previous
#include <cuda_runtime.h>
#include <cuda_fp16.h>
#include <math.h>
#include <stdint.h>

#define S_LEN 4096
#define DMODEL 768
#define NH 12
#define DK 64
#define XN (S_LEN * DMODEL)
#define WN (DMODEL * DMODEL)

__device__ __half g_xh[3 * XN];
__device__ __half g_wh[2 * WN], g_wl[2 * WN];
__device__ __half g_qh[XN], g_kh[XN], g_vh[XN];
__device__ __half g_ah[XN];

__device__ __forceinline__ uint32_t smem_u32(const void* p) {
    uint32_t a;
    asm("{ .reg .u64 t; cvta.to.shared.u64 t, %1; cvt.u32.u64 %0, t; }" : "=r"(a) : "l"(p));
    return a;
}
__device__ __forceinline__ float ex2f(float x) {
    float r; asm("ex2.approx.ftz.f32 %0, %1;" : "=f"(r) : "f"(x)); return r;
}
__device__ __forceinline__ uint32_t pack_f16(float a, float b) {  // low=a, high=b
    __half2 h = __floats2half2_rn(a, b);
    return *(uint32_t*)&h;
}
__device__ __forceinline__ void ldsm4(uint32_t* r, uint32_t a) {
    asm volatile("ldmatrix.sync.aligned.m8n8.x4.shared.b16 {%0,%1,%2,%3}, [%4];"
                 : "=r"(r[0]), "=r"(r[1]), "=r"(r[2]), "=r"(r[3]) : "r"(a));
}
__device__ __forceinline__ void ldsm4t(uint32_t* r, uint32_t a) {
    asm volatile("ldmatrix.sync.aligned.m8n8.x4.trans.shared.b16 {%0,%1,%2,%3}, [%4];"
                 : "=r"(r[0]), "=r"(r[1]), "=r"(r[2]), "=r"(r[3]) : "r"(a));
}
__device__ __forceinline__ void mma16816(float* d, const uint32_t* a, const uint32_t* b) {
    asm volatile("mma.sync.aligned.m16n8k16.row.col.f32.f16.f16.f32 "
                 "{%0,%1,%2,%3}, {%4,%5,%6,%7}, {%8,%9}, {%0,%1,%2,%3};"
                 : "+f"(d[0]), "+f"(d[1]), "+f"(d[2]), "+f"(d[3])
                 : "r"(a[0]), "r"(a[1]), "r"(a[2]), "r"(a[3]), "r"(b[0]), "r"(b[1]));
}
__device__ __forceinline__ void cp16(uint32_t d, const void* s) {
    asm volatile("cp.async.cg.shared.global [%0], [%1], 16;" :: "r"(d), "l"(s));
}
#define CP_COMMIT() asm volatile("cp.async.commit_group;" ::: "memory")
#define CP_WAIT0()  asm volatile("cp.async.wait_group 0;" ::: "memory")
#define CP_WAIT1()  asm volatile("cp.async.wait_group 1;" ::: "memory")

// fp32 -> fp16 (hi only), 3 tensors via grid.z
__global__ void conv_hi3(const float* __restrict__ a, const float* __restrict__ b,
                         const float* __restrict__ c, __half* __restrict__ hi, int n4)
{
    int i = blockIdx.x * blockDim.x + threadIdx.x;
    if (i >= n4) return;
    const float* in = (blockIdx.z == 0) ? a : (blockIdx.z == 1) ? b : c;
    size_t off = (size_t)blockIdx.z * n4 + i;
    float4 v = ((const float4*)in)[i];
    ((__half2*)hi)[2 * off]     = __floats2half2_rn(v.x, v.y);
    ((__half2*)hi)[2 * off + 1] = __floats2half2_rn(v.z, v.w);
}
// fp32 -> fp16 hi+lo, 2 tensors via grid.z (weights; lo needed for Wo)
__global__ void conv_hilo2(const float* __restrict__ a, const float* __restrict__ b,
                           __half* __restrict__ hi, __half* __restrict__ lo, int n4)
{
    int i = blockIdx.x * blockDim.x + threadIdx.x;
    if (i >= n4) return;
    const float* in = (blockIdx.z == 0) ? a : b;
    size_t off = (size_t)blockIdx.z * n4 + i;
    float4 v = ((const float4*)in)[i];
    __half2 h01 = __floats2half2_rn(v.x, v.y), h23 = __floats2half2_rn(v.z, v.w);
    ((__half2*)hi)[2 * off] = h01; ((__half2*)hi)[2 * off + 1] = h23;
    ((__half2*)lo)[2 * off]     = __floats2half2_rn(v.x - __half2float(h01.x), v.y - __half2float(h01.y));
    ((__half2*)lo)[2 * off + 1] = __floats2half2_rn(v.z - __half2float(h23.x), v.w - __half2float(h23.y));
}

// ---------------------------------------------------------------------------
// QKV projection: SINGLE-pass fp16 GEMM, 2 matrices per stage [X | W].
// ---------------------------------------------------------------------------
#define PM 5120
#define P1STG (2 * PM)
#define QKV_SMEM (2 * P1STG * 2)   // 40960 B

__device__ __forceinline__ void qkv_stage_load(
    __half* st, const __half* X, const __half* W, int m0, int n0, int k0, int tid)
{
    #pragma unroll
    for (int i = 0; i < 2; i++) {
        int idx = tid + i * 256;
        int r = idx >> 2, c8 = (idx & 3) * 8;
        uint32_t base = smem_u32(st + r * 40 + c8);
        cp16(base,          X + (size_t)(m0 + r) * DMODEL + k0 + c8);
        cp16(base + PM * 2, W + (size_t)(n0 + r) * DMODEL + k0 + c8);
    }
    CP_COMMIT();
}

__global__ void __launch_bounds__(256, 2) qkv_proj(
    const __half* __restrict__ xh, const __half* __restrict__ Wh,
    const float* __restrict__ bias,
    __half* __restrict__ Qh, __half* __restrict__ Kh, __half* __restrict__ Vh)
{
    extern __shared__ __half sm[];
    const int tid = threadIdx.x, w = tid >> 5, lid = tid & 31;
    const int wm = w >> 1, wn = w & 1;
    const int m0 = blockIdx.y * 128, n0 = blockIdx.x * 128, z = blockIdx.z;
    const __half* X = xh + (size_t)z * XN;
    __half* Yh = (z == 0) ? Qh : (z == 1) ? Kh : Vh;
    const float sc = (z == 0) ? 0.18033688011112042f : 1.0f;  // 0.125*log2(e)

    float acc[2][8][4] = {};
    qkv_stage_load(sm, X, Wh, m0, n0, 0, tid);
    for (int t = 0; t < DMODEL / 32; t++) {
        CP_WAIT0();
        __syncthreads();
        if (t + 1 < DMODEL / 32)
            qkv_stage_load(sm + ((t + 1) & 1) * P1STG, X, Wh, m0, n0, (t + 1) * 32, tid);
        __half* P0 = sm + (t & 1) * P1STG;
        __half* P1 = P0 + PM;
        #pragma unroll
        for (int ks = 0; ks < 32; ks += 16) {
            const int ac = ks + ((lid >> 4) << 3);
            uint32_t a1[2][4], b1[8][2], r4[4];
            #pragma unroll
            for (int jp = 0; jp < 4; jp++) {
                int rB = 64 * wn + 16 * jp + (lid & 15);
                ldsm4(r4, smem_u32(P1 + rB * 40 + ac));
                b1[2*jp][0]=r4[0]; b1[2*jp][1]=r4[2]; b1[2*jp+1][0]=r4[1]; b1[2*jp+1][1]=r4[3];
            }
            #pragma unroll
            for (int i = 0; i < 2; i++) {
                int rA = 32 * wm + 16 * i + (lid & 15);
                ldsm4(a1[i], smem_u32(P0 + rA * 40 + ac));
            }
            #pragma unroll
            for (int i = 0; i < 2; i++)
                #pragma unroll
                for (int j = 0; j < 8; j++) mma16816(acc[i][j], a1[i], b1[j]);
        }
        __syncthreads();
    }

    #pragma unroll
    for (int i = 0; i < 2; i++) {
        int r = m0 + 32 * wm + 16 * i + (lid >> 2);
        #pragma unroll
        for (int j = 0; j < 8; j++) {
            int ng = n0 + 64 * wn + 8 * j + (lid & 3) * 2;
            float b0 = bias[ng], b1 = bias[ng + 1];
            int head = ng >> 6;
            #pragma unroll
            for (int hrow = 0; hrow < 2; hrow++) {
                int rr = r + hrow * 8;
                float f0 = (acc[i][j][2*hrow]   + b0) * sc;
                float f1 = (acc[i][j][2*hrow+1] + b1) * sc;
                size_t dst = ((size_t)head * S_LEN + rr) * DK + (ng & 63);
                *(uint32_t*)(Yh + dst) = pack_f16(f0, f1);
            }
        }
    }
}

// ---------------------------------------------------------------------------
// Output projection: 2-pass Ah·(Wh+Wl), 3 matrices per stage.
// ---------------------------------------------------------------------------
#define PSTG (3 * PM)
#define PROJ_SMEM (2 * PSTG * 2)   // 61440 B

__device__ __forceinline__ void out_stage_load(
    __half* st, const __half* A, const __half* Wh, const __half* Wl,
    int m0, int n0, int k0, int tid)
{
    #pragma unroll
    for (int i = 0; i < 2; i++) {
        int idx = tid + i * 256;
        int r = idx >> 2, c8 = (idx & 3) * 8;
        size_t ms = (size_t)(m0 + r) * DMODEL + k0 + c8;
        size_t ns = (size_t)(n0 + r) * DMODEL + k0 + c8;
        uint32_t base = smem_u32(st + r * 40 + c8);
        cp16(base,              A + ms);
        cp16(base + PM * 2,     Wh + ns);
        cp16(base + 2 * PM * 2, Wl + ns);
    }
    CP_COMMIT();
}

__global__ void __launch_bounds__(256, 2) out_proj(
    const __half* __restrict__ Ah,
    const __half* __restrict__ Wh, const __half* __restrict__ Wl,
    const float* __restrict__ bias, float* __restrict__ Yf)
{
    extern __shared__ __half sm[];
    const int tid = threadIdx.x, w = tid >> 5, lid = tid & 31;
    const int wm = w >> 1, wn = w & 1;
    const int m0 = blockIdx.y * 128, n0 = blockIdx.x * 128;

    float acc[2][8][4] = {};
    out_stage_load(sm, Ah, Wh, Wl, m0, n0, 0, tid);
    for (int t = 0; t < DMODEL / 32; t++) {
        CP_WAIT0();
        __syncthreads();
        if (t + 1 < DMODEL / 32)
            out_stage_load(sm + ((t + 1) & 1) * PSTG, Ah, Wh, Wl, m0, n0, (t + 1) * 32, tid);
        __half* P0 = sm + (t & 1) * PSTG;
        __half* P1 = P0 + PM;
        __half* P2 = P0 + 2 * PM;
        #pragma unroll
        for (int ks = 0; ks < 32; ks += 16) {
            const int ac = ks + ((lid >> 4) << 3);
            uint32_t a1[2][4], b1[8][2], b2[8][2], r4[4];
            #pragma unroll
            for (int jp = 0; jp < 4; jp++) {
                int rB = 64 * wn + 16 * jp + (lid & 15);
                ldsm4(r4, smem_u32(P1 + rB * 40 + ac));
                b1[2*jp][0]=r4[0]; b1[2*jp][1]=r4[2]; b1[2*jp+1][0]=r4[1]; b1[2*jp+1][1]=r4[3];
                ldsm4(r4, smem_u32(P2 + rB * 40 + ac));
                b2[2*jp][0]=r4[0]; b2[2*jp][1]=r4[2]; b2[2*jp+1][0]=r4[1]; b2[2*jp+1][1]=r4[3];
            }
            #pragma unroll
            for (int i = 0; i < 2; i++) {
                int rA = 32 * wm + 16 * i + (lid & 15);
                ldsm4(a1[i], smem_u32(P0 + rA * 40 + ac));
            }
            #pragma unroll
            for (int i = 0; i < 2; i++) {
                #pragma unroll
                for (int j = 0; j < 8; j++) mma16816(acc[i][j], a1[i], b1[j]);
                #pragma unroll
                for (int j = 0; j < 8; j++) mma16816(acc[i][j], a1[i], b2[j]);
            }
        }
        __syncthreads();
    }

    #pragma unroll
    for (int i = 0; i < 2; i++) {
        int r = m0 + 32 * wm + 16 * i + (lid >> 2);
        #pragma unroll
        for (int j = 0; j < 8; j++) {
            int ng = n0 + 64 * wn + 8 * j + (lid & 3) * 2;
            float b0 = bias[ng], b1 = bias[ng + 1];
            #pragma unroll
            for (int hrow = 0; hrow < 2; hrow++) {
                int rr = r + hrow * 8;
                Yf[(size_t)rr * DMODEL + ng]     = acc[i][j][2*hrow]   + b0;
                Yf[(size_t)rr * DMODEL + ng + 1] = acc[i][j][2*hrow+1] + b1;
            }
        }
    }
}

// ---------------------------------------------------------------------------
// Flash attention: CTA=(head, 128 q rows), 8 warps, Bc=64, plain fp16.
// S = Qh·Kh (1 pass); O = Ph·Vh (1 pass). 64 MMA/tile/warp.
// 3-stage cp.async [Kh 64|Vh 64]; stage 2 overlays dead Q rows. smem 54KB.
// ---------------------------------------------------------------------------
#define QS 72
#define NT (S_LEN / 64)
#define AT_SMEM (384 * QS * 2)   // 55296 B

__device__ __forceinline__ void attn_stage_load(
    __half (*SN)[QS], const __half* Kh, const __half* Vh,
    size_t hbase, int kv0, int tid)
{
    #pragma unroll
    for (int i = 0; i < 2; i++) {
        int idx = tid + i * 256;
        int r = idx >> 3, c8 = (idx & 7) * 8;
        size_t src = hbase + (size_t)(kv0 + r) * DK + c8;
        cp16(smem_u32(&SN[r][c8]),      Kh + src);
        cp16(smem_u32(&SN[64 + r][c8]), Vh + src);
    }
    CP_COMMIT();
}

__global__ void __launch_bounds__(256, 2) attn_tc(
    const __half* __restrict__ Qh, const __half* __restrict__ Kh,
    const __half* __restrict__ Vh, __half* __restrict__ Ah)
{
    extern __shared__ __half sm[];
    __half (*ROWS)[QS] = (__half(*)[QS])sm;
    __half (*Qhs)[QS] = ROWS;                                  // rows 0..127
    __half (*stg[3])[QS] = { ROWS + 128, ROWS + 256, ROWS };   // S2 overlays Q

    const int tid = threadIdx.x, w = tid >> 5, lid = tid & 31;
    const int h = blockIdx.y, q0 = blockIdx.x * 128;
    const size_t hbase = (size_t)h * S_LEN * DK;

    #pragma unroll
    for (int i = 0; i < 2; i++) {               // Q: 512 uint4
        int idx = tid + i * 256;
        int r = idx >> 2, c8 = (idx & 3) * 16;
        size_t src = hbase + (size_t)(q0 + r) * DK + c8;
        *(uint4*)&Qhs[r][c8]     = *(const uint4*)(Qh + src);
        *(uint4*)&Qhs[r][c8 + 8] = *(const uint4*)(Qh + src + 8);
    }
    attn_stage_load(stg[0], Kh, Vh, hbase, 0,  tid);
    attn_stage_load(stg[1], Kh, Vh, hbase, 64, tid);
    __syncthreads();

    uint32_t qhf[4][4];
    #pragma unroll
    for (int ks = 0; ks < 4; ks++) {
        const int ac = 16 * ks + ((lid >> 4) << 3);
        ldsm4(qhf[ks], smem_u32(&Qhs[16 * w + (lid & 15)][ac]));
    }

    float O[8][4] = {};
    float m0r = -INFINITY, m1r = -INFINITY, l0r = 0.f, l1r = 0.f;

    for (int t = 0; t < NT; t++) {
        if (t == NT - 1) { CP_WAIT0(); } else { CP_WAIT1(); }
        __syncthreads();                // orders Q-hoist before S2 overwrite (t=0)
        if (t + 2 < NT)
            attn_stage_load(stg[(t + 2) % 3], Kh, Vh, hbase, (t + 2) * 64, tid);

        __half (*Khs)[QS] = stg[t % 3];
        __half (*Vhs)[QS] = Khs + 64;

        // S = Qh . Kh^T  -- 1 pass
        float s[8][4] = {};
        #pragma unroll
        for (int ks = 0; ks < 4; ks++) {
            const int ac = 16 * ks + ((lid >> 4) << 3);
            uint32_t bh[8][2], r4[4];
            #pragma unroll
            for (int jp = 0; jp < 4; jp++) {
                int rB = 16 * jp + (lid & 15);
                ldsm4(r4, smem_u32(&Khs[rB][ac]));
                bh[2*jp][0]=r4[0]; bh[2*jp][1]=r4[2]; bh[2*jp+1][0]=r4[1]; bh[2*jp+1][1]=r4[3];
            }
            #pragma unroll
            for (int j = 0; j < 8; j++) mma16816(s[j], qhf[ks], bh[j]);
        }

        // online softmax (log2 domain; scale folded into Q)
        float rm0 = -INFINITY, rm1 = -INFINITY;
        #pragma unroll
        for (int j = 0; j < 8; j++) {
            rm0 = fmaxf(rm0, fmaxf(s[j][0], s[j][1]));
            rm1 = fmaxf(rm1, fmaxf(s[j][2], s[j][3]));
        }
        rm0 = fmaxf(rm0, __shfl_xor_sync(~0u, rm0, 1)); rm0 = fmaxf(rm0, __shfl_xor_sync(~0u, rm0, 2));
        rm1 = fmaxf(rm1, __shfl_xor_sync(~0u, rm1, 1)); rm1 = fmaxf(rm1, __shfl_xor_sync(~0u, rm1, 2));
        float mn0 = fmaxf(m0r, rm0), mn1 = fmaxf(m1r, rm1);
        float c0 = ex2f(m0r - mn0), c1 = ex2f(m1r - mn1);
        m0r = mn0; m1r = mn1;
        float s0 = 0.f, s1 = 0.f;
        #pragma unroll
        for (int j = 0; j < 8; j++) {
            s[j][0] = ex2f(s[j][0] - mn0); s[j][1] = ex2f(s[j][1] - mn0);
            s[j][2] = ex2f(s[j][2] - mn1); s[j][3] = ex2f(s[j][3] - mn1);
            s0 += s[j][0] + s[j][1]; s1 += s[j][2] + s[j][3];
        }
        s0 += __shfl_xor_sync(~0u, s0, 1); s0 += __shfl_xor_sync(~0u, s0, 2);
        s1 += __shfl_xor_sync(~0u, s1, 1); s1 += __shfl_xor_sync(~0u, s1, 2);
        l0r = l0r * c0 + s0; l1r = l1r * c1 + s1;
        #pragma unroll
        for (int j = 0; j < 8; j++) { O[j][0] *= c0; O[j][1] *= c0; O[j][2] *= c1; O[j][3] *= c1; }

        // P -> fp16 A-fragments
        uint32_t ph[4][4];
        #pragma unroll
        for (int j2 = 0; j2 < 4; j2++) {
            int t0 = 2 * j2, t1 = t0 + 1;
            ph[j2][0] = pack_f16(s[t0][0], s[t0][1]); ph[j2][1] = pack_f16(s[t0][2], s[t0][3]);
            ph[j2][2] = pack_f16(s[t1][0], s[t1][1]); ph[j2][3] = pack_f16(s[t1][2], s[t1][3]);
        }

        // O += Ph . Vh  -- 1 pass
        #pragma unroll
        for (int j2 = 0; j2 < 4; j2++) {
            uint32_t vh[8][2], r4[4];
            #pragma unroll
            for (int np = 0; np < 4; np++) {
                int rV = 16 * j2 + (lid & 15), cV = 16 * np + ((lid >> 4) << 3);
                ldsm4t(r4, smem_u32(&Vhs[rV][cV]));
                vh[2*np][0]=r4[0]; vh[2*np][1]=r4[1]; vh[2*np+1][0]=r4[2]; vh[2*np+1][1]=r4[3];
            }
            #pragma unroll
            for (int tt = 0; tt < 8; tt++) mma16816(O[tt], ph[j2], vh[tt]);
        }
    }

    float i0 = 1.f / l0r, i1 = 1.f / l1r;
    #pragma unroll
    for (int t = 0; t < 8; t++) {
        int c = h * DK + 8 * t + (lid & 3) * 2;
        int r0 = q0 + 16 * w + (lid >> 2);
        #pragma unroll
        for (int hrow = 0; hrow < 2; hrow++) {
            float f0 = O[t][2*hrow]   * (hrow ? i1 : i0);
            float f1 = O[t][2*hrow+1] * (hrow ? i1 : i0);
            size_t dst = (size_t)(r0 + hrow * 8) * DMODEL + c;
            *(uint32_t*)(Ah + dst) = pack_f16(f0, f1);
        }
    }
}

extern "C" void kernel_launch(void* const* d_in, const int* in_sizes, int n_in,
                              void* d_out, int out_size)
{
    const float* q  = (const float*)d_in[0];
    const float* k  = (const float*)d_in[1];
    const float* v  = (const float*)d_in[2];
    const float* Wq = (const float*)d_in[3];
    const float* bq = (const float*)d_in[4];
    const float* Wo = (const float*)d_in[5];
    const float* bo = (const float*)d_in[6];
    float* out = (float*)d_out;

    __half *xh, *wh, *wl, *qh, *kh, *vh, *ah;
    cudaGetSymbolAddress((void**)&xh, g_xh);
    cudaGetSymbolAddress((void**)&wh, g_wh); cudaGetSymbolAddress((void**)&wl, g_wl);
    cudaGetSymbolAddress((void**)&qh, g_qh);
    cudaGetSymbolAddress((void**)&kh, g_kh); cudaGetSymbolAddress((void**)&vh, g_vh);
    cudaGetSymbolAddress((void**)&ah, g_ah);

    cudaFuncSetAttribute(attn_tc,  cudaFuncAttributeMaxDynamicSharedMemorySize, AT_SMEM);
    cudaFuncSetAttribute(qkv_proj, cudaFuncAttributeMaxDynamicSharedMemorySize, QKV_SMEM);
    cudaFuncSetAttribute(out_proj, cudaFuncAttributeMaxDynamicSharedMemorySize, PROJ_SMEM);

    dim3 gc3(XN / 4 / 256, 1, 3);
    conv_hi3<<<gc3, 256>>>(q, k, v, xh, XN / 4);
    dim3 gc2(WN / 4 / 256, 1, 2);
    conv_hilo2<<<gc2, 256>>>(Wq, Wo, wh, wl, WN / 4);

    dim3 gqkv(DMODEL / 128, S_LEN / 128, 3);   // 6 x 32 x 3
    qkv_proj<<<gqkv, 256, QKV_SMEM>>>(xh, wh, bq, qh, kh, vh);

    dim3 gattn(S_LEN / 128, NH);               // 32 x 12
    attn_tc<<<gattn, 256, AT_SMEM>>>(qh, kh, vh, ah);

    dim3 gout(DMODEL / 128, S_LEN / 128);      // 6 x 32
    out_proj<<<gout, 256, PROJ_SMEM>>>(ah, wh + WN, wl + WN, bo, out);
}